// round 3
// baseline (speedup 1.0000x reference)
#include <cuda_runtime.h>
#include <cuda_bf16.h>
#include <math.h>

#define Bc 64
#define Sc 128
#define Tc 64
#define Hc 512
#define Vc 32000

// ---------------- scratch (device globals: no allocs allowed) ----------------
__device__ float g_Uk[(size_t)Bc * Sc * Hc];   // 16 MB: Ua(keys) precompute
__device__ float g_h[Bc * Hc];                 // hidden state
__device__ float g_ctx[Bc * Hc];               // attention context
__device__ float g_hwa[Bc * Hc];               // h@Wa + ba
__device__ float g_scores[Bc * Sc];            // attention scores
__device__ float g_gi[Bc * 3 * Hc];            // x@W_ih^T
__device__ float g_gh[Bc * 3 * Hc];            // h@W_hh^T

__device__ __forceinline__ float sigm(float x) { return 1.0f / (1.0f + expf(-x)); }

// ---------------- init / final copies ----------------
__global__ void init_h_kernel(const float* __restrict__ src) {
    int i = blockIdx.x * 256 + threadIdx.x;
    if (i < Bc * Hc) g_h[i] = src[i];
}
__global__ void final_h_kernel(float* __restrict__ dst) {
    int i = blockIdx.x * 256 + threadIdx.x;
    if (i < Bc * Hc) dst[i] = g_h[i];
}

// ---------------- Uk = enc @ Ua + bu  (NN GEMM, M=8192,N=512,K=512) ----------
__global__ __launch_bounds__(256) void uk_gemm_kernel(
    const float* __restrict__ A,   // enc [8192,512]
    const float* __restrict__ Bm,  // Ua  [512,512]
    const float* __restrict__ bias)
{
    __shared__ float As[32][68];
    __shared__ float Bs[32][68];
    const int K = Hc, N = Hc;
    int tx = threadIdx.x & 15, ty = threadIdx.x >> 4;
    int n0 = blockIdx.x * 64, m0 = blockIdx.y * 64;
    float acc[4][4] = {};
    for (int k0 = 0; k0 < K; k0 += 32) {
        for (int i = threadIdx.x; i < 64 * 32; i += 256) {
            int r = i >> 5, kk = i & 31;
            As[kk][r] = A[(size_t)(m0 + r) * K + k0 + kk];
        }
        for (int i = threadIdx.x; i < 32 * 64; i += 256) {
            int kk = i >> 6, c = i & 63;
            Bs[kk][c] = Bm[(size_t)(k0 + kk) * N + n0 + c];
        }
        __syncthreads();
#pragma unroll
        for (int kk = 0; kk < 32; kk++) {
            float4 a = *(const float4*)&As[kk][ty * 4];
            float4 b = *(const float4*)&Bs[kk][tx * 4];
            float av[4] = {a.x, a.y, a.z, a.w};
            float bv[4] = {b.x, b.y, b.z, b.w};
#pragma unroll
            for (int i = 0; i < 4; i++)
#pragma unroll
                for (int j = 0; j < 4; j++) acc[i][j] += av[i] * bv[j];
        }
        __syncthreads();
    }
#pragma unroll
    for (int i = 0; i < 4; i++) {
        int r = m0 + ty * 4 + i;
#pragma unroll
        for (int j = 0; j < 4; j++) {
            int c = n0 + tx * 4 + j;
            g_Uk[(size_t)r * N + c] = acc[i][j] + bias[c];
        }
    }
}

// ---------------- hwa = h @ Wa + ba  (NN GEMM, M=64,N=512,K=512) -------------
// grid 16 blocks (N-tile 32), 256 threads, thread tile 4x2
__global__ __launch_bounds__(256) void hwa_kernel(
    const float* __restrict__ Wa, const float* __restrict__ ba)
{
    __shared__ float As[32][68];
    __shared__ float Bs[32][36];
    int tid = threadIdx.x;
    int tx = tid & 15, ty = tid >> 4;
    int n0 = blockIdx.x * 32;
    float acc[4][2] = {};
    for (int k0 = 0; k0 < Hc; k0 += 32) {
        for (int i = tid; i < 64 * 32; i += 256) {
            int r = i >> 5, kk = i & 31;
            As[kk][r] = g_h[r * Hc + k0 + kk];
        }
        for (int i = tid; i < 32 * 32; i += 256) {
            int kk = i >> 5, c = i & 31;
            Bs[kk][c] = Wa[(size_t)(k0 + kk) * Hc + n0 + c];
        }
        __syncthreads();
#pragma unroll
        for (int kk = 0; kk < 32; kk++) {
            float4 a = *(const float4*)&As[kk][ty * 4];
            float2 b = *(const float2*)&Bs[kk][tx * 2];
            acc[0][0] += a.x * b.x; acc[0][1] += a.x * b.y;
            acc[1][0] += a.y * b.x; acc[1][1] += a.y * b.y;
            acc[2][0] += a.z * b.x; acc[2][1] += a.z * b.y;
            acc[3][0] += a.w * b.x; acc[3][1] += a.w * b.y;
        }
        __syncthreads();
    }
#pragma unroll
    for (int i = 0; i < 4; i++) {
        int r = ty * 4 + i;
#pragma unroll
        for (int j = 0; j < 2; j++) {
            int c = n0 + tx * 2 + j;
            g_hwa[r * Hc + c] = acc[i][j] + ba[c];
        }
    }
}

// ---------------- scores[b][s] = sum_k tanh(hwa[b][k]+Uk[b][s][k])*Va[k] -----
// grid (8 chunks, 64 b), 128 threads (4 warps, 4 s each)
__global__ __launch_bounds__(128) void scores_kernel(const float* __restrict__ Va)
{
    int b = blockIdx.y, chunk = blockIdx.x;
    __shared__ float shwa[Hc];
    __shared__ float sva[Hc];
    int tid = threadIdx.x;
    for (int i = tid; i < Hc; i += 128) {
        shwa[i] = g_hwa[b * Hc + i];
        sva[i] = Va[i];
    }
    __syncthreads();
    int warp = tid >> 5, lane = tid & 31;
#pragma unroll
    for (int si = 0; si < 4; si++) {
        int s = chunk * 16 + warp * 4 + si;
        const float* uk = g_Uk + ((size_t)b * Sc + s) * Hc;
        float a0 = 0.f, a1 = 0.f;
#pragma unroll 4
        for (int k = lane; k < Hc; k += 64) {
            a0 += tanhf(shwa[k] + uk[k]) * sva[k];
            a1 += tanhf(shwa[k + 32] + uk[k + 32]) * sva[k + 32];
        }
        float a = a0 + a1;
#pragma unroll
        for (int o = 16; o; o >>= 1) a += __shfl_xor_sync(0xffffffffu, a, o);
        if (lane == 0) g_scores[b * Sc + s] = a;   // bv cancels in softmax
    }
}

// ---------------- softmax + ctx  (grid 64, 512 threads) ----------------------
__global__ __launch_bounds__(512) void softmax_ctx_kernel(
    const float* __restrict__ enc, float* __restrict__ att_out, int t)
{
    int b = blockIdx.x;
    __shared__ float sw[Sc];
    int tid = threadIdx.x;
    if (tid < Sc) sw[tid] = g_scores[b * Sc + tid];
    __syncthreads();
    int warp = tid >> 5, lane = tid & 31;
    if (warp == 0) {
        float v0 = sw[lane], v1 = sw[lane + 32], v2 = sw[lane + 64], v3 = sw[lane + 96];
        float m = fmaxf(fmaxf(v0, v1), fmaxf(v2, v3));
#pragma unroll
        for (int o = 16; o; o >>= 1) m = fmaxf(m, __shfl_xor_sync(0xffffffffu, m, o));
        float e0 = expf(v0 - m), e1 = expf(v1 - m), e2 = expf(v2 - m), e3 = expf(v3 - m);
        float s = e0 + e1 + e2 + e3;
#pragma unroll
        for (int o = 16; o; o >>= 1) s += __shfl_xor_sync(0xffffffffu, s, o);
        float inv = 1.0f / s;
        sw[lane] = e0 * inv; sw[lane + 32] = e1 * inv;
        sw[lane + 64] = e2 * inv; sw[lane + 96] = e3 * inv;
    }
    __syncthreads();

    if (tid < Sc) att_out[((size_t)b * Tc + t) * Sc + tid] = sw[tid];

    const float* encb = enc + (size_t)b * Sc * Hc;
    float c0 = 0.f, c1 = 0.f;
#pragma unroll 4
    for (int s = 0; s < Sc; s += 2) {
        c0 += sw[s] * encb[(size_t)s * Hc + tid];
        c1 += sw[s + 1] * encb[(size_t)(s + 1) * Hc + tid];
    }
    g_ctx[b * Hc + tid] = c0 + c1;
}

// ---------------- GRU GEMMs: gi = [e|ctx]@W_ih^T, gh = h@W_hh^T --------------
// grid 96: blocks 0..47 -> gi (K=1024), 48..95 -> gh (K=512). 64x32 tiles.
__global__ __launch_bounds__(256) void gru_gemm_kernel(
    const float* __restrict__ emb, const int* __restrict__ tgt,
    const float* __restrict__ W_ih, const float* __restrict__ W_hh, int t)
{
    bool is_gi = blockIdx.x < 48;
    int n0 = (is_gi ? blockIdx.x : blockIdx.x - 48) * 32;
    const int K = is_gi ? 2 * Hc : Hc;
    const float* W = is_gi ? W_ih : W_hh;
    float* out = is_gi ? g_gi : g_gh;

    __shared__ float As[32][68];
    __shared__ float Bs[32][36];
    __shared__ int stok[64];
    int tid = threadIdx.x;
    if (is_gi && tid < 64) stok[tid] = (t == 0) ? 0 : tgt[tid * Tc + t - 1];
    __syncthreads();

    int tx = tid & 15, ty = tid >> 4;
    float acc[4][2] = {};
    for (int k0 = 0; k0 < K; k0 += 32) {
        for (int i = tid; i < 64 * 32; i += 256) {
            int r = i >> 5, kk = i & 31;
            int k = k0 + kk;
            float v;
            if (is_gi)
                v = (k < Hc) ? emb[(size_t)stok[r] * Hc + k] : g_ctx[r * Hc + k - Hc];
            else
                v = g_h[r * Hc + k];
            As[kk][r] = v;
        }
        for (int i = tid; i < 32 * 32; i += 256) {
            int c = i >> 5, kk = i & 31;
            Bs[kk][c] = W[(size_t)(n0 + c) * K + k0 + kk];
        }
        __syncthreads();
#pragma unroll
        for (int kk = 0; kk < 32; kk++) {
            float4 a = *(const float4*)&As[kk][ty * 4];
            float2 b = *(const float2*)&Bs[kk][tx * 2];
            acc[0][0] += a.x * b.x; acc[0][1] += a.x * b.y;
            acc[1][0] += a.y * b.x; acc[1][1] += a.y * b.y;
            acc[2][0] += a.z * b.x; acc[2][1] += a.z * b.y;
            acc[3][0] += a.w * b.x; acc[3][1] += a.w * b.y;
        }
        __syncthreads();
    }
#pragma unroll
    for (int i = 0; i < 4; i++) {
        int r = ty * 4 + i;
#pragma unroll
        for (int j = 0; j < 2; j++) {
            int c = n0 + tx * 2 + j;
            out[r * (3 * Hc) + c] = acc[i][j];
        }
    }
}

// ---------------- GRU gates (grid 64, 512 threads) ---------------------------
__global__ __launch_bounds__(512) void gates_kernel(
    const float* __restrict__ b_ih, const float* __restrict__ b_hh)
{
    int b = blockIdx.x, j = threadIdx.x;
    const float* gi = g_gi + b * 3 * Hc;
    const float* gh = g_gh + b * 3 * Hc;
    float gir = gi[j] + b_ih[j];
    float ghr = gh[j] + b_hh[j];
    float giz = gi[Hc + j] + b_ih[Hc + j];
    float ghz = gh[Hc + j] + b_hh[Hc + j];
    float gin = gi[2 * Hc + j] + b_ih[2 * Hc + j];
    float ghn = gh[2 * Hc + j] + b_hh[2 * Hc + j];
    float r = sigm(gir + ghr);
    float z = sigm(giz + ghz);
    float n = tanhf(gin + r * ghn);
    float hprev = g_h[b * Hc + j];
    g_h[b * Hc + j] = (1.0f - z) * n + z * hprev;
}

// ---------------- logits = h_new @ Wout^T + bout  (NT, M=64,N=32000,K=512) ---
// 64x128 tiles, 250 blocks, 256 threads, thread tile 4x8, float4 smem traffic
__global__ __launch_bounds__(256) void logits_kernel(
    const float* __restrict__ Wout, const float* __restrict__ bout,
    float* __restrict__ C /* d_out + t*V */)
{
    __shared__ float As[32][68];
    __shared__ float Bs[32][132];
    int tid = threadIdx.x;
    int tx = tid & 15, ty = tid >> 4;
    int n0 = blockIdx.x * 128;
    float acc[4][8] = {};
    for (int k0 = 0; k0 < Hc; k0 += 32) {
        // As: 64 rows x 32 k  (512 float4 loads, 2 per thread)
        for (int i = tid; i < 512; i += 256) {
            int r = i >> 3, kq = i & 7;
            float4 v = *(const float4*)&g_h[r * Hc + k0 + kq * 4];
            As[kq * 4 + 0][r] = v.x;
            As[kq * 4 + 1][r] = v.y;
            As[kq * 4 + 2][r] = v.z;
            As[kq * 4 + 3][r] = v.w;
        }
        // Bs: 128 cols x 32 k  (1024 float4 loads, 4 per thread)
        for (int i = tid; i < 1024; i += 256) {
            int c = i >> 3, kq = i & 7;
            float4 v = *(const float4*)&Wout[(size_t)(n0 + c) * Hc + k0 + kq * 4];
            Bs[kq * 4 + 0][c] = v.x;
            Bs[kq * 4 + 1][c] = v.y;
            Bs[kq * 4 + 2][c] = v.z;
            Bs[kq * 4 + 3][c] = v.w;
        }
        __syncthreads();
#pragma unroll
        for (int kk = 0; kk < 32; kk++) {
            float4 a = *(const float4*)&As[kk][ty * 4];
            float4 b0 = *(const float4*)&Bs[kk][tx * 8];
            float4 b1 = *(const float4*)&Bs[kk][tx * 8 + 4];
            float av[4] = {a.x, a.y, a.z, a.w};
            float bv[8] = {b0.x, b0.y, b0.z, b0.w, b1.x, b1.y, b1.z, b1.w};
#pragma unroll
            for (int i = 0; i < 4; i++)
#pragma unroll
                for (int j = 0; j < 8; j++) acc[i][j] += av[i] * bv[j];
        }
        __syncthreads();
    }
    const size_t ldc = (size_t)Tc * Vc;
    float4 bo0 = *(const float4*)&bout[n0 + tx * 8];
    float4 bo1 = *(const float4*)&bout[n0 + tx * 8 + 4];
#pragma unroll
    for (int i = 0; i < 4; i++) {
        int r = ty * 4 + i;
        float* crow = C + (size_t)r * ldc + n0 + tx * 8;
        float4 o0 = make_float4(acc[i][0] + bo0.x, acc[i][1] + bo0.y,
                                acc[i][2] + bo0.z, acc[i][3] + bo0.w);
        float4 o1 = make_float4(acc[i][4] + bo1.x, acc[i][5] + bo1.y,
                                acc[i][6] + bo1.z, acc[i][7] + bo1.w);
        *(float4*)crow = o0;
        *(float4*)(crow + 4) = o1;
    }
}

// ---------------- in-place log_softmax over V per batch row ------------------
__global__ __launch_bounds__(512) void lsm_kernel(float* __restrict__ Cbase)
{
    int b = blockIdx.x;
    float* row = Cbase + (size_t)b * Tc * Vc;
    __shared__ float red[16];
    int tid = threadIdx.x, lane = tid & 31, w = tid >> 5;

    float m = -3.4e38f;
    for (int v = tid; v < Vc; v += 512) m = fmaxf(m, row[v]);
#pragma unroll
    for (int o = 16; o; o >>= 1) m = fmaxf(m, __shfl_xor_sync(0xffffffffu, m, o));
    if (lane == 0) red[w] = m;
    __syncthreads();
    float bm = red[0];
#pragma unroll
    for (int i = 1; i < 16; i++) bm = fmaxf(bm, red[i]);
    __syncthreads();

    float s = 0.f;
    for (int v = tid; v < Vc; v += 512) s += __expf(row[v] - bm);
#pragma unroll
    for (int o = 16; o; o >>= 1) s += __shfl_xor_sync(0xffffffffu, s, o);
    if (lane == 0) red[w] = s;
    __syncthreads();
    float tot = 0.f;
#pragma unroll
    for (int i = 0; i < 16; i++) tot += red[i];

    float ls = bm + logf(tot);
    for (int v = tid; v < Vc; v += 512) row[v] -= ls;
}

// ---------------- launch ----------------
extern "C" void kernel_launch(void* const* d_in, const int* in_sizes, int n_in,
                              void* d_out, int out_size)
{
    const float* enc  = (const float*)d_in[0];
    const float* h0   = (const float*)d_in[1];
    const int*   tgt  = (const int*)d_in[2];
    const float* emb  = (const float*)d_in[3];
    const float* Wa   = (const float*)d_in[4];
    const float* ba   = (const float*)d_in[5];
    const float* Ua   = (const float*)d_in[6];
    const float* bu   = (const float*)d_in[7];
    const float* Va   = (const float*)d_in[8];
    /* d_in[9] = bv : cancels inside softmax, never observable */
    const float* W_ih = (const float*)d_in[10];
    const float* W_hh = (const float*)d_in[11];
    const float* b_ih = (const float*)d_in[12];
    const float* b_hh = (const float*)d_in[13];
    const float* Wout = (const float*)d_in[14];
    const float* bout = (const float*)d_in[15];

    float* out  = (float*)d_out;
    float* logp = out;                                    // [B,T,V]
    float* hf   = out + (size_t)Bc * Tc * Vc;             // [1,B,H]
    float* att  = hf + (size_t)Bc * Hc;                   // [B,T,S]

    // Uk precompute: [B*S, H] = enc @ Ua + bu
    dim3 gUk(Hc / 64, (Bc * Sc) / 64);
    uk_gemm_kernel<<<gUk, 256>>>(enc, Ua, bu);

    // h <- encoder_hidden[0]
    init_h_kernel<<<(Bc * Hc + 255) / 256, 256>>>(h0);

    for (int t = 0; t < Tc; t++) {
        hwa_kernel<<<16, 256>>>(Wa, ba);
        scores_kernel<<<dim3(8, Bc), 128>>>(Va);
        softmax_ctx_kernel<<<Bc, 512>>>(enc, att, t);
        gru_gemm_kernel<<<96, 256>>>(emb, tgt, W_ih, W_hh, t);
        gates_kernel<<<Bc, 512>>>(b_ih, b_hh);
        logits_kernel<<<Vc / 128, 256>>>(Wout, bout, logp + (size_t)t * Vc);
        lsm_kernel<<<Bc, 512>>>(logp + (size_t)t * Vc);
    }

    final_h_kernel<<<(Bc * Hc + 255) / 256, 256>>>(hf);
}

// round 4
// speedup vs baseline: 1.8160x; 1.8160x over previous
#include <cuda_runtime.h>
#include <cuda_bf16.h>
#include <math.h>
#include <stdint.h>

#define Bc 64
#define Sc 128
#define Tc 64
#define Hc 512
#define Vc 32000

typedef __nv_bfloat16 bf16;

// ---------------- scratch (device globals: no allocs allowed) ----------------
__device__ __align__(16) float g_Uk[(size_t)Bc * Sc * Hc];     // 16 MB
__device__ __align__(16) float g_h[Bc * Hc];
__device__ __align__(16) bf16  g_hhi[Bc * Hc], g_hlo[Bc * Hc];
__device__ __align__(16) float g_hwa[Bc * Hc];
__device__ __align__(16) float g_scores[Bc * Sc];
__device__ __align__(16) float g_w[Bc * Sc];
__device__ __align__(16) float g_gi[Bc * 3 * Hc], g_gh[Bc * 3 * Hc];
__device__ __align__(16) bf16  g_xhi[(size_t)Tc * Bc * 2 * Hc];   // 8.4 MB
__device__ __align__(16) bf16  g_xlo[(size_t)Tc * Bc * 2 * Hc];
__device__ __align__(16) bf16  g_WoutH[(size_t)Vc * Hc], g_WoutL[(size_t)Vc * Hc]; // 32.8MB ea
__device__ __align__(16) bf16  g_WihH[3 * Hc * 2 * Hc], g_WihL[3 * Hc * 2 * Hc];
__device__ __align__(16) bf16  g_WhhH[3 * Hc * Hc],     g_WhhL[3 * Hc * Hc];
__device__ __align__(16) bf16  g_WaTH[Hc * Hc], g_WaTL[Hc * Hc];
__device__ __align__(16) bf16  g_UaTH[Hc * Hc], g_UaTL[Hc * Hc];
__device__ __align__(16) bf16  g_encH[(size_t)Bc * Sc * Hc], g_encL[(size_t)Bc * Sc * Hc];

__device__ __forceinline__ float sigm(float x) { return 1.0f / (1.0f + expf(-x)); }
__device__ __forceinline__ void split2(float x, bf16* hi, bf16* lo) {
    bf16 h = __float2bfloat16(x);
    *hi = h;
    *lo = __float2bfloat16(x - __bfloat162float(h));
}

// ---------------- conversion kernels ----------------
__global__ void split_kernel(const float* __restrict__ src, bf16* __restrict__ hi,
                             bf16* __restrict__ lo, int n)
{
    int i = (blockIdx.x * 256 + threadIdx.x) * 4;
    if (i >= n) return;
    float4 v = *(const float4*)(src + i);
    split2(v.x, hi + i + 0, lo + i + 0);
    split2(v.y, hi + i + 1, lo + i + 1);
    split2(v.z, hi + i + 2, lo + i + 2);
    split2(v.w, hi + i + 3, lo + i + 3);
}

// transpose-convert 512x512: dst[n][k] = src[k][n]
__global__ void splitT_kernel(const float* __restrict__ src, bf16* __restrict__ hi,
                              bf16* __restrict__ lo)
{
    int idx = blockIdx.x * 256 + threadIdx.x;   // over 262144
    int k = idx >> 9, n = idx & 511;
    split2(src[idx], hi + n * Hc + k, lo + n * Hc + k);
}

__global__ void inith_kernel(const float* __restrict__ h0) {
    int i = blockIdx.x * 256 + threadIdx.x;
    if (i < Bc * Hc) {
        float v = h0[i];
        g_h[i] = v;
        split2(v, g_hhi + i, g_hlo + i);
    }
}
__global__ void final_h_kernel(float* __restrict__ dst) {
    int i = blockIdx.x * 256 + threadIdx.x;
    if (i < Bc * Hc) dst[i] = g_h[i];
}

// embedding gather + split for ALL steps: x[t][b][0:H] = emb[tok(t,b)]
__global__ void xe_kernel(const float* __restrict__ emb, const int* __restrict__ tgt) {
    int t = blockIdx.x, b = blockIdx.y;
    int tok = (t == 0) ? 0 : tgt[b * Tc + t - 1];
    size_t base = ((size_t)t * Bc + b) * (2 * Hc);
    const float* e = emb + (size_t)tok * Hc;
    for (int k = threadIdx.x; k < Hc; k += 128)
        split2(e[k], g_xhi + base + k, g_xlo + base + k);
}

// ---------------- generic split-bf16 NT MMA: out[M,N] = A[M,K] @ B[N,K]^T ----
// block tile 64(M) x 128(N), KC=32, 8 warps (4 M x 2 N), warp tile 16x64
#define MMA_BF16(c, a, b0_, b1_)                                           \
    asm volatile(                                                          \
        "mma.sync.aligned.m16n8k16.row.col.f32.bf16.bf16.f32 "             \
        "{%0,%1,%2,%3},{%4,%5,%6,%7},{%8,%9},{%0,%1,%2,%3};"               \
        : "+f"(c[0]), "+f"(c[1]), "+f"(c[2]), "+f"(c[3])                   \
        : "r"(a[0]), "r"(a[1]), "r"(a[2]), "r"(a[3]), "r"(b0_), "r"(b1_))

__global__ __launch_bounds__(256) void mma_nt_kernel(
    const bf16* __restrict__ Ahi, const bf16* __restrict__ Alo,
    const bf16* __restrict__ Bhi, const bf16* __restrict__ Blo,
    const float* __restrict__ bias, float* __restrict__ out,
    int K, size_t ldc)
{
    const int LDA = 40;   // padded row stride (bf16) -> conflict-free, 16B aligned
    __shared__ __align__(16) bf16 AsH[64 * 40], AsL[64 * 40];
    __shared__ __align__(16) bf16 BsH[128 * 40], BsL[128 * 40];

    int tid = threadIdx.x, lane = tid & 31, wid = tid >> 5;
    int g = lane >> 2, t4 = lane & 3;
    int wy = wid & 3, wx = wid >> 2;
    int m0 = blockIdx.y * 64, n0 = blockIdx.x * 128;

    float acc[8][4] = {};

    for (int k0 = 0; k0 < K; k0 += 32) {
        // A: 64x32 -> 256 x 16B, 1 per thread
        {
            int m = tid >> 2, c8 = (tid & 3) * 8;
            size_t go = (size_t)(m0 + m) * K + k0 + c8;
            *(uint4*)&AsH[m * LDA + c8] = *(const uint4*)(Ahi + go);
            *(uint4*)&AsL[m * LDA + c8] = *(const uint4*)(Alo + go);
        }
        // B: 128x32 -> 512 x 16B, 2 per thread
        for (int i = tid; i < 512; i += 256) {
            int n = i >> 2, c8 = (i & 3) * 8;
            size_t go = (size_t)(n0 + n) * K + k0 + c8;
            *(uint4*)&BsH[n * LDA + c8] = *(const uint4*)(Bhi + go);
            *(uint4*)&BsL[n * LDA + c8] = *(const uint4*)(Blo + go);
        }
        __syncthreads();
#pragma unroll
        for (int kf = 0; kf < 2; kf++) {
            int kk = kf * 16;
            int ar0 = (wy * 16 + g) * LDA + kk + t4 * 2;
            int ar1 = (wy * 16 + g + 8) * LDA + kk + t4 * 2;
            uint32_t aH[4], aL[4];
            aH[0] = *(uint32_t*)&AsH[ar0];     aH[1] = *(uint32_t*)&AsH[ar1];
            aH[2] = *(uint32_t*)&AsH[ar0 + 8]; aH[3] = *(uint32_t*)&AsH[ar1 + 8];
            aL[0] = *(uint32_t*)&AsL[ar0];     aL[1] = *(uint32_t*)&AsL[ar1];
            aL[2] = *(uint32_t*)&AsL[ar0 + 8]; aL[3] = *(uint32_t*)&AsL[ar1 + 8];
#pragma unroll
            for (int nf = 0; nf < 8; nf++) {
                int br = (wx * 64 + nf * 8 + g) * LDA + kk + t4 * 2;
                uint32_t bH0 = *(uint32_t*)&BsH[br], bH1 = *(uint32_t*)&BsH[br + 8];
                uint32_t bL0 = *(uint32_t*)&BsL[br], bL1 = *(uint32_t*)&BsL[br + 8];
                MMA_BF16(acc[nf], aH, bH0, bH1);   // hi*hi
                MMA_BF16(acc[nf], aH, bL0, bL1);   // hi*lo
                MMA_BF16(acc[nf], aL, bH0, bH1);   // lo*hi
            }
        }
        __syncthreads();
    }

    int mrow0 = m0 + wy * 16 + g, mrow1 = mrow0 + 8;
#pragma unroll
    for (int nf = 0; nf < 8; nf++) {
        int col = n0 + wx * 64 + nf * 8 + t4 * 2;
        float b0 = bias ? bias[col] : 0.f;
        float b1 = bias ? bias[col + 1] : 0.f;
        out[(size_t)mrow0 * ldc + col]     = acc[nf][0] + b0;
        out[(size_t)mrow0 * ldc + col + 1] = acc[nf][1] + b1;
        out[(size_t)mrow1 * ldc + col]     = acc[nf][2] + b0;
        out[(size_t)mrow1 * ldc + col + 1] = acc[nf][3] + b1;
    }
}

// ---------------- scores: one warp per (b,s) -------------------------------
__global__ __launch_bounds__(256) void scores_kernel(const float* __restrict__ Va)
{
    int b = blockIdx.y;
    __shared__ float shwa[Hc], sva[Hc];
    int tid = threadIdx.x;
    for (int i = tid; i < Hc; i += 256) { shwa[i] = g_hwa[b * Hc + i]; sva[i] = Va[i]; }
    __syncthreads();
    int warp = tid >> 5, lane = tid & 31;
    int s = blockIdx.x * 8 + warp;
    const float* uk = g_Uk + ((size_t)b * Sc + s) * Hc;
    float acc = 0.f;
#pragma unroll
    for (int j = 0; j < 4; j++) {
        int k = j * 128 + lane * 4;
        float4 u  = *(const float4*)(uk + k);
        float4 wv = *(const float4*)(shwa + k);
        float4 vv = *(const float4*)(sva + k);
        acc += tanhf(wv.x + u.x) * vv.x + tanhf(wv.y + u.y) * vv.y
             + tanhf(wv.z + u.z) * vv.z + tanhf(wv.w + u.w) * vv.w;
    }
#pragma unroll
    for (int o = 16; o; o >>= 1) acc += __shfl_xor_sync(0xffffffffu, acc, o);
    if (!lane) g_scores[b * Sc + s] = acc;   // bv cancels in softmax
}

// ---------------- softmax over S=128, write weights + attn output -----------
__global__ void softmaxw_kernel(float* __restrict__ att_out, int t)
{
    int b = blockIdx.x, tid = threadIdx.x;   // 128 threads
    __shared__ float sw[Sc];
    sw[tid] = g_scores[b * Sc + tid];
    __syncthreads();
    if (tid < 32) {
        float v0 = sw[tid], v1 = sw[tid + 32], v2 = sw[tid + 64], v3 = sw[tid + 96];
        float m = fmaxf(fmaxf(v0, v1), fmaxf(v2, v3));
#pragma unroll
        for (int o = 16; o; o >>= 1) m = fmaxf(m, __shfl_xor_sync(0xffffffffu, m, o));
        float e0 = expf(v0 - m), e1 = expf(v1 - m), e2 = expf(v2 - m), e3 = expf(v3 - m);
        float s = e0 + e1 + e2 + e3;
#pragma unroll
        for (int o = 16; o; o >>= 1) s += __shfl_xor_sync(0xffffffffu, s, o);
        float inv = 1.0f / s;
        sw[tid] = e0 * inv; sw[tid + 32] = e1 * inv;
        sw[tid + 64] = e2 * inv; sw[tid + 96] = e3 * inv;
    }
    __syncthreads();
    float w = sw[tid];
    g_w[b * Sc + tid] = w;
    att_out[((size_t)b * Tc + t) * Sc + tid] = w;
}

// ---------------- ctx[b][col] = sum_s w[s]*enc[b][s][col]; write x-tail bf16 -
__global__ void ctx_kernel(const float* __restrict__ enc, int t)
{
    int b = blockIdx.y, col = blockIdx.x * 128 + threadIdx.x;
    __shared__ float w[Sc];
    w[threadIdx.x] = g_w[b * Sc + threadIdx.x];
    __syncthreads();
    const float* encb = enc + (size_t)b * Sc * Hc + col;
    float acc = 0.f;
#pragma unroll 8
    for (int s = 0; s < Sc; s++) acc += w[s] * encb[(size_t)s * Hc];
    size_t base = ((size_t)t * Bc + b) * (2 * Hc) + Hc + col;
    split2(acc, g_xhi + base, g_xlo + base);
}

// ---------------- GRU gates: h_new from gi/gh; also split h for mma ---------
__global__ void gates_kernel(const float* __restrict__ b_ih, const float* __restrict__ b_hh)
{
    int b = blockIdx.x, j = threadIdx.x;
    const float* gi = g_gi + b * 3 * Hc;
    const float* gh = g_gh + b * 3 * Hc;
    float r = sigm(gi[j] + b_ih[j] + gh[j] + b_hh[j]);
    float z = sigm(gi[Hc + j] + b_ih[Hc + j] + gh[Hc + j] + b_hh[Hc + j]);
    float n = tanhf(gi[2 * Hc + j] + b_ih[2 * Hc + j] + r * (gh[2 * Hc + j] + b_hh[2 * Hc + j]));
    float hp = g_h[b * Hc + j];
    float hn = (1.0f - z) * n + z * hp;
    g_h[b * Hc + j] = hn;
    split2(hn, g_hhi + b * Hc + j, g_hlo + b * Hc + j);
}

// ---------------- in-place log_softmax over V per batch row ------------------
__global__ __launch_bounds__(512) void lsm_kernel(float* __restrict__ Cbase)
{
    int b = blockIdx.x;
    float* row = Cbase + (size_t)b * Tc * Vc;
    __shared__ float red[16];
    int tid = threadIdx.x, lane = tid & 31, w = tid >> 5;

    float m = -3.4e38f;
    for (int v = tid; v < Vc; v += 512) m = fmaxf(m, row[v]);
#pragma unroll
    for (int o = 16; o; o >>= 1) m = fmaxf(m, __shfl_xor_sync(0xffffffffu, m, o));
    if (lane == 0) red[w] = m;
    __syncthreads();
    float bm = red[0];
#pragma unroll
    for (int i = 1; i < 16; i++) bm = fmaxf(bm, red[i]);
    __syncthreads();

    float s = 0.f;
    for (int v = tid; v < Vc; v += 512) s += __expf(row[v] - bm);
#pragma unroll
    for (int o = 16; o; o >>= 1) s += __shfl_xor_sync(0xffffffffu, s, o);
    if (lane == 0) red[w] = s;
    __syncthreads();
    float tot = 0.f;
#pragma unroll
    for (int i = 0; i < 16; i++) tot += red[i];

    float ls = bm + logf(tot);
    for (int v = tid; v < Vc; v += 512) row[v] -= ls;
}

// ---------------- launch ----------------
extern "C" void kernel_launch(void* const* d_in, const int* in_sizes, int n_in,
                              void* d_out, int out_size)
{
    const float* enc  = (const float*)d_in[0];
    const float* h0   = (const float*)d_in[1];
    const int*   tgt  = (const int*)d_in[2];
    const float* emb  = (const float*)d_in[3];
    const float* Wa   = (const float*)d_in[4];
    const float* ba   = (const float*)d_in[5];
    const float* Ua   = (const float*)d_in[6];
    const float* bu   = (const float*)d_in[7];
    const float* Va   = (const float*)d_in[8];
    /* d_in[9] = bv : cancels inside softmax, never observable */
    const float* W_ih = (const float*)d_in[10];
    const float* W_hh = (const float*)d_in[11];
    const float* b_ih = (const float*)d_in[12];
    const float* b_hh = (const float*)d_in[13];
    const float* Wout = (const float*)d_in[14];
    const float* bout = (const float*)d_in[15];

    float* out  = (float*)d_out;
    float* logp = out;                                    // [B,T,V]
    float* hf   = out + (size_t)Bc * Tc * Vc;             // [1,B,H]
    float* att  = hf + (size_t)Bc * Hc;                   // [B,T,S]

    // resolve device-global addresses
    void *p_WoutH, *p_WoutL, *p_WihH, *p_WihL, *p_WhhH, *p_WhhL;
    void *p_WaTH, *p_WaTL, *p_UaTH, *p_UaTL, *p_encH, *p_encL;
    void *p_hhi, *p_hlo, *p_xhi, *p_xlo, *p_Uk, *p_hwa, *p_gi, *p_gh;
    cudaGetSymbolAddress(&p_WoutH, g_WoutH); cudaGetSymbolAddress(&p_WoutL, g_WoutL);
    cudaGetSymbolAddress(&p_WihH, g_WihH);   cudaGetSymbolAddress(&p_WihL, g_WihL);
    cudaGetSymbolAddress(&p_WhhH, g_WhhH);   cudaGetSymbolAddress(&p_WhhL, g_WhhL);
    cudaGetSymbolAddress(&p_WaTH, g_WaTH);   cudaGetSymbolAddress(&p_WaTL, g_WaTL);
    cudaGetSymbolAddress(&p_UaTH, g_UaTH);   cudaGetSymbolAddress(&p_UaTL, g_UaTL);
    cudaGetSymbolAddress(&p_encH, g_encH);   cudaGetSymbolAddress(&p_encL, g_encL);
    cudaGetSymbolAddress(&p_hhi, g_hhi);     cudaGetSymbolAddress(&p_hlo, g_hlo);
    cudaGetSymbolAddress(&p_xhi, g_xhi);     cudaGetSymbolAddress(&p_xlo, g_xlo);
    cudaGetSymbolAddress(&p_Uk, g_Uk);       cudaGetSymbolAddress(&p_hwa, g_hwa);
    cudaGetSymbolAddress(&p_gi, g_gi);       cudaGetSymbolAddress(&p_gh, g_gh);

    // weight conversions (every replay; ~15us total)
    split_kernel<<<(Vc * Hc) / 1024, 256>>>(Wout, (bf16*)p_WoutH, (bf16*)p_WoutL, Vc * Hc);
    split_kernel<<<(3 * Hc * 2 * Hc) / 1024, 256>>>(W_ih, (bf16*)p_WihH, (bf16*)p_WihL, 3 * Hc * 2 * Hc);
    split_kernel<<<(3 * Hc * Hc) / 1024, 256>>>(W_hh, (bf16*)p_WhhH, (bf16*)p_WhhL, 3 * Hc * Hc);
    split_kernel<<<(Bc * Sc * Hc) / 1024, 256>>>(enc, (bf16*)p_encH, (bf16*)p_encL, Bc * Sc * Hc);
    splitT_kernel<<<(Hc * Hc) / 256, 256>>>(Wa, (bf16*)p_WaTH, (bf16*)p_WaTL);
    splitT_kernel<<<(Hc * Hc) / 256, 256>>>(Ua, (bf16*)p_UaTH, (bf16*)p_UaTL);

    inith_kernel<<<(Bc * Hc + 255) / 256, 256>>>(h0);
    xe_kernel<<<dim3(Tc, Bc), 128>>>(emb, tgt);

    // Uk = enc @ Ua + bu : M=8192 (grid.y=128), N=512 (grid.x=4), K=512
    mma_nt_kernel<<<dim3(4, 128), 256>>>((bf16*)p_encH, (bf16*)p_encL,
                                         (bf16*)p_UaTH, (bf16*)p_UaTL,
                                         bu, (float*)p_Uk, Hc, (size_t)Hc);

    for (int t = 0; t < Tc; t++) {
        // hwa = h @ Wa + ba
        mma_nt_kernel<<<dim3(4, 1), 256>>>((bf16*)p_hhi, (bf16*)p_hlo,
                                           (bf16*)p_WaTH, (bf16*)p_WaTL,
                                           ba, (float*)p_hwa, Hc, (size_t)Hc);
        // gh = h @ W_hh^T (biases added in gates)
        mma_nt_kernel<<<dim3(12, 1), 256>>>((bf16*)p_hhi, (bf16*)p_hlo,
                                            (bf16*)p_WhhH, (bf16*)p_WhhL,
                                            nullptr, (float*)p_gh, Hc, (size_t)(3 * Hc));
        scores_kernel<<<dim3(16, Bc), 256>>>(Va);
        softmaxw_kernel<<<Bc, 128>>>(att, t);
        ctx_kernel<<<dim3(4, Bc), 128>>>(enc, t);
        // gi = x @ W_ih^T, x = [e|ctx] (K=1024)
        mma_nt_kernel<<<dim3(12, 1), 256>>>(
            (bf16*)p_xhi + (size_t)t * Bc * 2 * Hc, (bf16*)p_xlo + (size_t)t * Bc * 2 * Hc,
            (bf16*)p_WihH, (bf16*)p_WihL,
            nullptr, (float*)p_gi, 2 * Hc, (size_t)(3 * Hc));
        gates_kernel<<<Bc, Hc>>>(b_ih, b_hh);
        // logits = h_new @ Wout^T + bout -> d_out slice
        mma_nt_kernel<<<dim3(Vc / 128, 1), 256>>>((bf16*)p_hhi, (bf16*)p_hlo,
                                                  (bf16*)p_WoutH, (bf16*)p_WoutL,
                                                  bout, logp + (size_t)t * Vc,
                                                  Hc, (size_t)Tc * Vc);
        lsm_kernel<<<Bc, 512>>>(logp + (size_t)t * Vc);
    }

    final_h_kernel<<<(Bc * Hc + 255) / 256, 256>>>(hf);
}

// round 5
// speedup vs baseline: 1.8274x; 1.0063x over previous
#include <cuda_runtime.h>
#include <cuda_bf16.h>
#include <math.h>
#include <stdint.h>

#define Bc 64
#define Sc 128
#define Tc 64
#define Hc 512
#define Vc 32000

typedef __nv_bfloat16 bf16;

// ---------------- scratch (device globals: no allocs allowed) ----------------
__device__ __align__(16) float g_Uk[(size_t)Bc * Sc * Hc];     // 16 MB
__device__ __align__(16) float g_h[Bc * Hc];
__device__ __align__(16) bf16  g_hhi[Bc * Hc], g_hlo[Bc * Hc];
__device__ __align__(16) float g_hwa[Bc * Hc];
__device__ __align__(16) float g_scores[Bc * Sc];
__device__ __align__(16) float g_w[Bc * Sc];
__device__ __align__(16) float g_gi[Bc * 3 * Hc], g_gh[Bc * 3 * Hc];
__device__ __align__(16) bf16  g_xhi[(size_t)Tc * Bc * 2 * Hc];   // 8.4 MB
__device__ __align__(16) bf16  g_xlo[(size_t)Tc * Bc * 2 * Hc];
__device__ __align__(16) bf16  g_WoutH[(size_t)Vc * Hc], g_WoutL[(size_t)Vc * Hc]; // 32.8MB ea
__device__ __align__(16) bf16  g_WihH[3 * Hc * 2 * Hc], g_WihL[3 * Hc * 2 * Hc];
__device__ __align__(16) bf16  g_WhhH[3 * Hc * Hc],     g_WhhL[3 * Hc * Hc];
__device__ __align__(16) bf16  g_WaTH[Hc * Hc], g_WaTL[Hc * Hc];
__device__ __align__(16) bf16  g_UaTH[Hc * Hc], g_UaTL[Hc * Hc];
__device__ __align__(16) bf16  g_encH[(size_t)Bc * Sc * Hc], g_encL[(size_t)Bc * Sc * Hc];

__device__ __forceinline__ float sigm(float x) { return 1.0f / (1.0f + expf(-x)); }
__device__ __forceinline__ void split2(float x, bf16* hi, bf16* lo) {
    bf16 h = __float2bfloat16(x);
    *hi = h;
    *lo = __float2bfloat16(x - __bfloat162float(h));
}

// ---------------- conversion kernels ----------------
__global__ void split_kernel(const float* __restrict__ src, bf16* __restrict__ hi,
                             bf16* __restrict__ lo, int n)
{
    int i = (blockIdx.x * 256 + threadIdx.x) * 4;
    if (i >= n) return;
    float4 v = *(const float4*)(src + i);
    split2(v.x, hi + i + 0, lo + i + 0);
    split2(v.y, hi + i + 1, lo + i + 1);
    split2(v.z, hi + i + 2, lo + i + 2);
    split2(v.w, hi + i + 3, lo + i + 3);
}

// transpose-convert 512x512: dst[n][k] = src[k][n]
__global__ void splitT_kernel(const float* __restrict__ src, bf16* __restrict__ hi,
                              bf16* __restrict__ lo)
{
    int idx = blockIdx.x * 256 + threadIdx.x;   // over 262144
    int k = idx >> 9, n = idx & 511;
    split2(src[idx], hi + n * Hc + k, lo + n * Hc + k);
}

__global__ void inith_kernel(const float* __restrict__ h0) {
    int i = blockIdx.x * 256 + threadIdx.x;
    if (i < Bc * Hc) {
        float v = h0[i];
        g_h[i] = v;
        split2(v, g_hhi + i, g_hlo + i);
    }
}
__global__ void final_h_kernel(float* __restrict__ dst) {
    int i = blockIdx.x * 256 + threadIdx.x;
    if (i < Bc * Hc) dst[i] = g_h[i];
}

// embedding gather + split for ALL steps: x[t][b][0:H] = emb[tok(t,b)]
__global__ void xe_kernel(const float* __restrict__ emb, const int* __restrict__ tgt) {
    int t = blockIdx.x, b = blockIdx.y;
    int tok = (t == 0) ? 0 : tgt[b * Tc + t - 1];
    size_t base = ((size_t)t * Bc + b) * (2 * Hc);
    const float* e = emb + (size_t)tok * Hc;
    for (int k = threadIdx.x; k < Hc; k += 128)
        split2(e[k], g_xhi + base + k, g_xlo + base + k);
}

// ---------------- generic split-bf16 NT MMA: out[M,N] = A[M,K] @ B[N,K]^T ----
// block tile 64(M) x 128(N), KC=32, 8 warps (4 M x 2 N), warp tile 16x64
#define MMA_BF16(c, a, b0_, b1_)                                           \
    asm volatile(                                                          \
        "mma.sync.aligned.m16n8k16.row.col.f32.bf16.bf16.f32 "             \
        "{%0,%1,%2,%3},{%4,%5,%6,%7},{%8,%9},{%0,%1,%2,%3};"               \
        : "+f"(c[0]), "+f"(c[1]), "+f"(c[2]), "+f"(c[3])                   \
        : "r"(a[0]), "r"(a[1]), "r"(a[2]), "r"(a[3]), "r"(b0_), "r"(b1_))

__global__ __launch_bounds__(256) void mma_nt_kernel(
    const bf16* __restrict__ Ahi, const bf16* __restrict__ Alo,
    const bf16* __restrict__ Bhi, const bf16* __restrict__ Blo,
    const float* __restrict__ bias, float* __restrict__ out,
    int K, size_t ldc)
{
    const int LDA = 40;   // padded row stride (bf16) -> conflict-free, 16B aligned
    __shared__ __align__(16) bf16 AsH[64 * 40], AsL[64 * 40];
    __shared__ __align__(16) bf16 BsH[128 * 40], BsL[128 * 40];

    int tid = threadIdx.x, lane = tid & 31, wid = tid >> 5;
    int g = lane >> 2, t4 = lane & 3;
    int wy = wid & 3, wx = wid >> 2;
    int m0 = blockIdx.y * 64, n0 = blockIdx.x * 128;

    float acc[8][4] = {};

    for (int k0 = 0; k0 < K; k0 += 32) {
        // A: 64x32 -> 256 x 16B, 1 per thread
        {
            int m = tid >> 2, c8 = (tid & 3) * 8;
            size_t go = (size_t)(m0 + m) * K + k0 + c8;
            *(uint4*)&AsH[m * LDA + c8] = *(const uint4*)(Ahi + go);
            *(uint4*)&AsL[m * LDA + c8] = *(const uint4*)(Alo + go);
        }
        // B: 128x32 -> 512 x 16B, 2 per thread
        for (int i = tid; i < 512; i += 256) {
            int n = i >> 2, c8 = (i & 3) * 8;
            size_t go = (size_t)(n0 + n) * K + k0 + c8;
            *(uint4*)&BsH[n * LDA + c8] = *(const uint4*)(Bhi + go);
            *(uint4*)&BsL[n * LDA + c8] = *(const uint4*)(Blo + go);
        }
        __syncthreads();
#pragma unroll
        for (int kf = 0; kf < 2; kf++) {
            int kk = kf * 16;
            int ar0 = (wy * 16 + g) * LDA + kk + t4 * 2;
            int ar1 = (wy * 16 + g + 8) * LDA + kk + t4 * 2;
            uint32_t aH[4], aL[4];
            aH[0] = *(uint32_t*)&AsH[ar0];     aH[1] = *(uint32_t*)&AsH[ar1];
            aH[2] = *(uint32_t*)&AsH[ar0 + 8]; aH[3] = *(uint32_t*)&AsH[ar1 + 8];
            aL[0] = *(uint32_t*)&AsL[ar0];     aL[1] = *(uint32_t*)&AsL[ar1];
            aL[2] = *(uint32_t*)&AsL[ar0 + 8]; aL[3] = *(uint32_t*)&AsL[ar1 + 8];
#pragma unroll
            for (int nf = 0; nf < 8; nf++) {
                int br = (wx * 64 + nf * 8 + g) * LDA + kk + t4 * 2;
                uint32_t bH0 = *(uint32_t*)&BsH[br], bH1 = *(uint32_t*)&BsH[br + 8];
                uint32_t bL0 = *(uint32_t*)&BsL[br], bL1 = *(uint32_t*)&BsL[br + 8];
                MMA_BF16(acc[nf], aH, bH0, bH1);   // hi*hi
                MMA_BF16(acc[nf], aH, bL0, bL1);   // hi*lo
                MMA_BF16(acc[nf], aL, bH0, bH1);   // lo*hi
            }
        }
        __syncthreads();
    }

    int mrow0 = m0 + wy * 16 + g, mrow1 = mrow0 + 8;
#pragma unroll
    for (int nf = 0; nf < 8; nf++) {
        int col = n0 + wx * 64 + nf * 8 + t4 * 2;
        float b0 = bias ? bias[col] : 0.f;
        float b1 = bias ? bias[col + 1] : 0.f;
        out[(size_t)mrow0 * ldc + col]     = acc[nf][0] + b0;
        out[(size_t)mrow0 * ldc + col + 1] = acc[nf][1] + b1;
        out[(size_t)mrow1 * ldc + col]     = acc[nf][2] + b0;
        out[(size_t)mrow1 * ldc + col + 1] = acc[nf][3] + b1;
    }
}

// ---------------- scores: one warp per (b,s) -------------------------------
__global__ __launch_bounds__(256) void scores_kernel(const float* __restrict__ Va)
{
    int b = blockIdx.y;
    __shared__ float shwa[Hc], sva[Hc];
    int tid = threadIdx.x;
    for (int i = tid; i < Hc; i += 256) { shwa[i] = g_hwa[b * Hc + i]; sva[i] = Va[i]; }
    __syncthreads();
    int warp = tid >> 5, lane = tid & 31;
    int s = blockIdx.x * 8 + warp;
    const float* uk = g_Uk + ((size_t)b * Sc + s) * Hc;
    float acc = 0.f;
#pragma unroll
    for (int j = 0; j < 4; j++) {
        int k = j * 128 + lane * 4;
        float4 u  = *(const float4*)(uk + k);
        float4 wv = *(const float4*)(shwa + k);
        float4 vv = *(const float4*)(sva + k);
        acc += tanhf(wv.x + u.x) * vv.x + tanhf(wv.y + u.y) * vv.y
             + tanhf(wv.z + u.z) * vv.z + tanhf(wv.w + u.w) * vv.w;
    }
#pragma unroll
    for (int o = 16; o; o >>= 1) acc += __shfl_xor_sync(0xffffffffu, acc, o);
    if (!lane) g_scores[b * Sc + s] = acc;   // bv cancels in softmax
}

// ---------------- softmax over S=128, write weights + attn output -----------
__global__ void softmaxw_kernel(float* __restrict__ att_out, int t)
{
    int b = blockIdx.x, tid = threadIdx.x;   // 128 threads
    __shared__ float sw[Sc];
    sw[tid] = g_scores[b * Sc + tid];
    __syncthreads();
    if (tid < 32) {
        float v0 = sw[tid], v1 = sw[tid + 32], v2 = sw[tid + 64], v3 = sw[tid + 96];
        float m = fmaxf(fmaxf(v0, v1), fmaxf(v2, v3));
#pragma unroll
        for (int o = 16; o; o >>= 1) m = fmaxf(m, __shfl_xor_sync(0xffffffffu, m, o));
        float e0 = expf(v0 - m), e1 = expf(v1 - m), e2 = expf(v2 - m), e3 = expf(v3 - m);
        float s = e0 + e1 + e2 + e3;
#pragma unroll
        for (int o = 16; o; o >>= 1) s += __shfl_xor_sync(0xffffffffu, s, o);
        float inv = 1.0f / s;
        sw[tid] = e0 * inv; sw[tid + 32] = e1 * inv;
        sw[tid + 64] = e2 * inv; sw[tid + 96] = e3 * inv;
    }
    __syncthreads();
    float w = sw[tid];
    g_w[b * Sc + tid] = w;
    att_out[((size_t)b * Tc + t) * Sc + tid] = w;
}

// ---------------- ctx[b][col] = sum_s w[s]*enc[b][s][col]; write x-tail bf16 -
__global__ void ctx_kernel(const float* __restrict__ enc, int t)
{
    int b = blockIdx.y, col = blockIdx.x * 128 + threadIdx.x;
    __shared__ float w[Sc];
    w[threadIdx.x] = g_w[b * Sc + threadIdx.x];
    __syncthreads();
    const float* encb = enc + (size_t)b * Sc * Hc + col;
    float acc = 0.f;
#pragma unroll 8
    for (int s = 0; s < Sc; s++) acc += w[s] * encb[(size_t)s * Hc];
    size_t base = ((size_t)t * Bc + b) * (2 * Hc) + Hc + col;
    split2(acc, g_xhi + base, g_xlo + base);
}

// ---------------- GRU gates: h_new from gi/gh; also split h for mma ---------
__global__ void gates_kernel(const float* __restrict__ b_ih, const float* __restrict__ b_hh)
{
    int b = blockIdx.x, j = threadIdx.x;
    const float* gi = g_gi + b * 3 * Hc;
    const float* gh = g_gh + b * 3 * Hc;
    float r = sigm(gi[j] + b_ih[j] + gh[j] + b_hh[j]);
    float z = sigm(gi[Hc + j] + b_ih[Hc + j] + gh[Hc + j] + b_hh[Hc + j]);
    float n = tanhf(gi[2 * Hc + j] + b_ih[2 * Hc + j] + r * (gh[2 * Hc + j] + b_hh[2 * Hc + j]));
    float hp = g_h[b * Hc + j];
    float hn = (1.0f - z) * n + z * hp;
    g_h[b * Hc + j] = hn;
    split2(hn, g_hhi + b * Hc + j, g_hlo + b * Hc + j);
}

// ---------------- in-place log_softmax over V per batch row ------------------
__global__ __launch_bounds__(512) void lsm_kernel(float* __restrict__ Cbase)
{
    int b = blockIdx.x;
    float* row = Cbase + (size_t)b * Tc * Vc;
    __shared__ float red[16];
    int tid = threadIdx.x, lane = tid & 31, w = tid >> 5;

    float m = -3.4e38f;
    for (int v = tid; v < Vc; v += 512) m = fmaxf(m, row[v]);
#pragma unroll
    for (int o = 16; o; o >>= 1) m = fmaxf(m, __shfl_xor_sync(0xffffffffu, m, o));
    if (lane == 0) red[w] = m;
    __syncthreads();
    float bm = red[0];
#pragma unroll
    for (int i = 1; i < 16; i++) bm = fmaxf(bm, red[i]);
    __syncthreads();

    float s = 0.f;
    for (int v = tid; v < Vc; v += 512) s += __expf(row[v] - bm);
#pragma unroll
    for (int o = 16; o; o >>= 1) s += __shfl_xor_sync(0xffffffffu, s, o);
    if (lane == 0) red[w] = s;
    __syncthreads();
    float tot = 0.f;
#pragma unroll
    for (int i = 0; i < 16; i++) tot += red[i];

    float ls = bm + logf(tot);
    for (int v = tid; v < Vc; v += 512) row[v] -= ls;
}

// ---------------- launch ----------------
extern "C" void kernel_launch(void* const* d_in, const int* in_sizes, int n_in,
                              void* d_out, int out_size)
{
    const float* enc  = (const float*)d_in[0];
    const float* h0   = (const float*)d_in[1];
    const int*   tgt  = (const int*)d_in[2];
    const float* emb  = (const float*)d_in[3];
    const float* Wa   = (const float*)d_in[4];
    const float* ba   = (const float*)d_in[5];
    const float* Ua   = (const float*)d_in[6];
    const float* bu   = (const float*)d_in[7];
    const float* Va   = (const float*)d_in[8];
    /* d_in[9] = bv : cancels inside softmax, never observable */
    const float* W_ih = (const float*)d_in[10];
    const float* W_hh = (const float*)d_in[11];
    const float* b_ih = (const float*)d_in[12];
    const float* b_hh = (const float*)d_in[13];
    const float* Wout = (const float*)d_in[14];
    const float* bout = (const float*)d_in[15];

    float* out  = (float*)d_out;
    float* logp = out;                                    // [B,T,V]
    float* hf   = out + (size_t)Bc * Tc * Vc;             // [1,B,H]
    float* att  = hf + (size_t)Bc * Hc;                   // [B,T,S]

    // resolve device-global addresses
    void *p_WoutH, *p_WoutL, *p_WihH, *p_WihL, *p_WhhH, *p_WhhL;
    void *p_WaTH, *p_WaTL, *p_UaTH, *p_UaTL, *p_encH, *p_encL;
    void *p_hhi, *p_hlo, *p_xhi, *p_xlo, *p_Uk, *p_hwa, *p_gi, *p_gh;
    cudaGetSymbolAddress(&p_WoutH, g_WoutH); cudaGetSymbolAddress(&p_WoutL, g_WoutL);
    cudaGetSymbolAddress(&p_WihH, g_WihH);   cudaGetSymbolAddress(&p_WihL, g_WihL);
    cudaGetSymbolAddress(&p_WhhH, g_WhhH);   cudaGetSymbolAddress(&p_WhhL, g_WhhL);
    cudaGetSymbolAddress(&p_WaTH, g_WaTH);   cudaGetSymbolAddress(&p_WaTL, g_WaTL);
    cudaGetSymbolAddress(&p_UaTH, g_UaTH);   cudaGetSymbolAddress(&p_UaTL, g_UaTL);
    cudaGetSymbolAddress(&p_encH, g_encH);   cudaGetSymbolAddress(&p_encL, g_encL);
    cudaGetSymbolAddress(&p_hhi, g_hhi);     cudaGetSymbolAddress(&p_hlo, g_hlo);
    cudaGetSymbolAddress(&p_xhi, g_xhi);     cudaGetSymbolAddress(&p_xlo, g_xlo);
    cudaGetSymbolAddress(&p_Uk, g_Uk);       cudaGetSymbolAddress(&p_hwa, g_hwa);
    cudaGetSymbolAddress(&p_gi, g_gi);       cudaGetSymbolAddress(&p_gh, g_gh);

    // weight conversions (every replay; ~15us total)
    split_kernel<<<(Vc * Hc) / 1024, 256>>>(Wout, (bf16*)p_WoutH, (bf16*)p_WoutL, Vc * Hc);
    split_kernel<<<(3 * Hc * 2 * Hc) / 1024, 256>>>(W_ih, (bf16*)p_WihH, (bf16*)p_WihL, 3 * Hc * 2 * Hc);
    split_kernel<<<(3 * Hc * Hc) / 1024, 256>>>(W_hh, (bf16*)p_WhhH, (bf16*)p_WhhL, 3 * Hc * Hc);
    split_kernel<<<(Bc * Sc * Hc) / 1024, 256>>>(enc, (bf16*)p_encH, (bf16*)p_encL, Bc * Sc * Hc);
    splitT_kernel<<<(Hc * Hc) / 256, 256>>>(Wa, (bf16*)p_WaTH, (bf16*)p_WaTL);
    splitT_kernel<<<(Hc * Hc) / 256, 256>>>(Ua, (bf16*)p_UaTH, (bf16*)p_UaTL);

    inith_kernel<<<(Bc * Hc + 255) / 256, 256>>>(h0);
    xe_kernel<<<dim3(Tc, Bc), 128>>>(emb, tgt);

    // Uk = enc @ Ua + bu : M=8192 (grid.y=128), N=512 (grid.x=4), K=512
    mma_nt_kernel<<<dim3(4, 128), 256>>>((bf16*)p_encH, (bf16*)p_encL,
                                         (bf16*)p_UaTH, (bf16*)p_UaTL,
                                         bu, (float*)p_Uk, Hc, (size_t)Hc);

    for (int t = 0; t < Tc; t++) {
        // hwa = h @ Wa + ba
        mma_nt_kernel<<<dim3(4, 1), 256>>>((bf16*)p_hhi, (bf16*)p_hlo,
                                           (bf16*)p_WaTH, (bf16*)p_WaTL,
                                           ba, (float*)p_hwa, Hc, (size_t)Hc);
        // gh = h @ W_hh^T (biases added in gates)
        mma_nt_kernel<<<dim3(12, 1), 256>>>((bf16*)p_hhi, (bf16*)p_hlo,
                                            (bf16*)p_WhhH, (bf16*)p_WhhL,
                                            nullptr, (float*)p_gh, Hc, (size_t)(3 * Hc));
        scores_kernel<<<dim3(16, Bc), 256>>>(Va);
        softmaxw_kernel<<<Bc, 128>>>(att, t);
        ctx_kernel<<<dim3(4, Bc), 128>>>(enc, t);
        // gi = x @ W_ih^T, x = [e|ctx] (K=1024)
        mma_nt_kernel<<<dim3(12, 1), 256>>>(
            (bf16*)p_xhi + (size_t)t * Bc * 2 * Hc, (bf16*)p_xlo + (size_t)t * Bc * 2 * Hc,
            (bf16*)p_WihH, (bf16*)p_WihL,
            nullptr, (float*)p_gi, 2 * Hc, (size_t)(3 * Hc));
        gates_kernel<<<Bc, Hc>>>(b_ih, b_hh);
        // logits = h_new @ Wout^T + bout -> d_out slice
        mma_nt_kernel<<<dim3(Vc / 128, 1), 256>>>((bf16*)p_hhi, (bf16*)p_hlo,
                                                  (bf16*)p_WoutH, (bf16*)p_WoutL,
                                                  bout, logp + (size_t)t * Vc,
                                                  Hc, (size_t)Tc * Vc);
        lsm_kernel<<<Bc, 512>>>(logp + (size_t)t * Vc);
    }

    final_h_kernel<<<(Bc * Hc + 255) / 256, 256>>>(hf);
}

// round 6
// speedup vs baseline: 4.0554x; 2.2193x over previous
#include <cuda_runtime.h>
#include <cuda_bf16.h>
#include <math.h>
#include <stdint.h>

#define Bc 64
#define Sc 128
#define Tc 64
#define Hc 512
#define Vc 32000

typedef __nv_bfloat16 bf16;

// ---------------- scratch (device globals: no allocs allowed) ----------------
__device__ __align__(16) float g_Uk[(size_t)Bc * Sc * Hc];       // 16 MB
__device__ __align__(16) float g_h[Bc * Hc];
__device__ __align__(16) bf16  g_hhi[Bc * Hc], g_hlo[Bc * Hc];
__device__ __align__(16) float g_hwagh[Bc * 2048];               // [hwa(512)|gh(1536)]
__device__ __align__(16) float g_s2[2 * Bc * Sc];                // K-split partial scores
__device__ __align__(16) float g_w[Bc * Sc];
__device__ __align__(16) float g_giC[Bc * 3 * Hc];
__device__ __align__(16) float g_giE[(size_t)Tc * Bc * 3 * Hc];  // 25 MB
__device__ __align__(16) bf16  g_xeH[(size_t)Tc * Bc * Hc], g_xeL[(size_t)Tc * Bc * Hc];
__device__ __align__(16) bf16  g_ctxH[Bc * Hc], g_ctxL[Bc * Hc];
__device__ __align__(16) bf16  g_hallH[(size_t)Tc * Bc * Hc], g_hallL[(size_t)Tc * Bc * Hc];
__device__ __align__(16) bf16  g_WoutH[(size_t)Vc * Hc], g_WoutL[(size_t)Vc * Hc];
__device__ __align__(16) bf16  g_BcatH[2048 * Hc], g_BcatL[2048 * Hc]; // [WaT|W_hh]
__device__ __align__(16) bf16  g_WihEH[3 * Hc * Hc], g_WihEL[3 * Hc * Hc]; // W_ih[:, :H]
__device__ __align__(16) bf16  g_WihCH[3 * Hc * Hc], g_WihCL[3 * Hc * Hc]; // W_ih[:, H:]
__device__ __align__(16) bf16  g_UaTH[Hc * Hc], g_UaTL[Hc * Hc];
__device__ __align__(16) bf16  g_encH[(size_t)Bc * Sc * Hc], g_encL[(size_t)Bc * Sc * Hc];

__device__ __forceinline__ float sigm(float x) { return 1.0f / (1.0f + expf(-x)); }
__device__ __forceinline__ void split2(float x, bf16* hi, bf16* lo) {
    bf16 h = __float2bfloat16(x);
    *hi = h;
    *lo = __float2bfloat16(x - __bfloat162float(h));
}

// ---------------- conversion kernels ----------------
__global__ void split_kernel(const float* __restrict__ src, bf16* __restrict__ hi,
                             bf16* __restrict__ lo, int n)
{
    int i = (blockIdx.x * 256 + threadIdx.x) * 4;
    if (i >= n) return;
    float4 v = *(const float4*)(src + i);
    split2(v.x, hi + i + 0, lo + i + 0);
    split2(v.y, hi + i + 1, lo + i + 1);
    split2(v.z, hi + i + 2, lo + i + 2);
    split2(v.w, hi + i + 3, lo + i + 3);
}

// transpose-convert 512x512: dst[n][k] = src[k][n]
__global__ void splitT_kernel(const float* __restrict__ src, bf16* __restrict__ hi,
                              bf16* __restrict__ lo)
{
    int idx = blockIdx.x * 256 + threadIdx.x;
    int k = idx >> 9, n = idx & 511;
    split2(src[idx], hi + n * Hc + k, lo + n * Hc + k);
}

// pack W_ih [1536,1024] into E part (cols 0..511) and C part (cols 512..1023)
__global__ void splitWih_kernel(const float* __restrict__ W)
{
    int idx = blockIdx.x * 256 + threadIdx.x;   // over 1536*512
    int r = idx >> 9, c = idx & 511;
    split2(W[(size_t)r * 1024 + c], g_WihEH + idx, g_WihEL + idx);
    split2(W[(size_t)r * 1024 + 512 + c], g_WihCH + idx, g_WihCL + idx);
}

__global__ void inith_kernel(const float* __restrict__ h0) {
    int i = blockIdx.x * 256 + threadIdx.x;
    if (i < Bc * Hc) {
        float v = h0[i];
        g_h[i] = v;
        split2(v, g_hhi + i, g_hlo + i);
    }
}
__global__ void final_h_kernel(float* __restrict__ dst) {
    int i = blockIdx.x * 256 + threadIdx.x;
    if (i < Bc * Hc) dst[i] = g_h[i];
}

// embedding gather + split for ALL steps: xe[t*64+b] = emb[tok(t,b)]
__global__ void xe_kernel(const float* __restrict__ emb, const int* __restrict__ tgt) {
    int t = blockIdx.x, b = blockIdx.y;
    int tok = (t == 0) ? 0 : tgt[b * Tc + t - 1];
    size_t base = ((size_t)t * Bc + b) * Hc;
    const float* e = emb + (size_t)tok * Hc;
    for (int k = threadIdx.x; k < Hc; k += 128)
        split2(e[k], g_xeH + base + k, g_xeL + base + k);
}

// ---------------- generic split-bf16 NT MMA: out[M,N] = A[M,K] @ B[N,K]^T ----
// block tile 64(M) x 128(N), KC=32, 8 warps (4 M x 2 N)
// scatter==1: output row m -> ((m&63)*Tc + (m>>6))*Vc   (logits -> [B,T,V])
#define MMA_BF16(c, a, b0_, b1_)                                           \
    asm volatile(                                                          \
        "mma.sync.aligned.m16n8k16.row.col.f32.bf16.bf16.f32 "             \
        "{%0,%1,%2,%3},{%4,%5,%6,%7},{%8,%9},{%0,%1,%2,%3};"               \
        : "+f"(c[0]), "+f"(c[1]), "+f"(c[2]), "+f"(c[3])                   \
        : "r"(a[0]), "r"(a[1]), "r"(a[2]), "r"(a[3]), "r"(b0_), "r"(b1_))

__global__ __launch_bounds__(256) void mma_nt_kernel(
    const bf16* __restrict__ Ahi, const bf16* __restrict__ Alo,
    const bf16* __restrict__ Bhi, const bf16* __restrict__ Blo,
    const float* __restrict__ bias, float* __restrict__ out,
    int K, size_t ldc, int scatter)
{
    const int LDA = 40;
    __shared__ __align__(16) bf16 AsH[64 * 40], AsL[64 * 40];
    __shared__ __align__(16) bf16 BsH[128 * 40], BsL[128 * 40];

    int tid = threadIdx.x, lane = tid & 31, wid = tid >> 5;
    int g = lane >> 2, t4 = lane & 3;
    int wy = wid & 3, wx = wid >> 2;
    int m0 = blockIdx.y * 64, n0 = blockIdx.x * 128;

    float acc[8][4] = {};

    for (int k0 = 0; k0 < K; k0 += 32) {
        {
            int m = tid >> 2, c8 = (tid & 3) * 8;
            size_t go = (size_t)(m0 + m) * K + k0 + c8;
            *(uint4*)&AsH[m * LDA + c8] = *(const uint4*)(Ahi + go);
            *(uint4*)&AsL[m * LDA + c8] = *(const uint4*)(Alo + go);
        }
        for (int i = tid; i < 512; i += 256) {
            int n = i >> 2, c8 = (i & 3) * 8;
            size_t go = (size_t)(n0 + n) * K + k0 + c8;
            *(uint4*)&BsH[n * LDA + c8] = *(const uint4*)(Bhi + go);
            *(uint4*)&BsL[n * LDA + c8] = *(const uint4*)(Blo + go);
        }
        __syncthreads();
#pragma unroll
        for (int kf = 0; kf < 2; kf++) {
            int kk = kf * 16;
            int ar0 = (wy * 16 + g) * LDA + kk + t4 * 2;
            int ar1 = (wy * 16 + g + 8) * LDA + kk + t4 * 2;
            uint32_t aH[4], aL[4];
            aH[0] = *(uint32_t*)&AsH[ar0];     aH[1] = *(uint32_t*)&AsH[ar1];
            aH[2] = *(uint32_t*)&AsH[ar0 + 8]; aH[3] = *(uint32_t*)&AsH[ar1 + 8];
            aL[0] = *(uint32_t*)&AsL[ar0];     aL[1] = *(uint32_t*)&AsL[ar1];
            aL[2] = *(uint32_t*)&AsL[ar0 + 8]; aL[3] = *(uint32_t*)&AsL[ar1 + 8];
#pragma unroll
            for (int nf = 0; nf < 8; nf++) {
                int br = (wx * 64 + nf * 8 + g) * LDA + kk + t4 * 2;
                uint32_t bH0 = *(uint32_t*)&BsH[br], bH1 = *(uint32_t*)&BsH[br + 8];
                uint32_t bL0 = *(uint32_t*)&BsL[br], bL1 = *(uint32_t*)&BsL[br + 8];
                MMA_BF16(acc[nf], aH, bH0, bH1);
                MMA_BF16(acc[nf], aH, bL0, bL1);
                MMA_BF16(acc[nf], aL, bH0, bH1);
            }
        }
        __syncthreads();
    }

    int mr0 = m0 + wy * 16 + g, mr1 = mr0 + 8;
    size_t ro0, ro1;
    if (scatter) {
        ro0 = ((size_t)(mr0 & 63) * Tc + (mr0 >> 6)) * Vc;
        ro1 = ((size_t)(mr1 & 63) * Tc + (mr1 >> 6)) * Vc;
    } else {
        ro0 = (size_t)mr0 * ldc;
        ro1 = (size_t)mr1 * ldc;
    }
#pragma unroll
    for (int nf = 0; nf < 8; nf++) {
        int col = n0 + wx * 64 + nf * 8 + t4 * 2;
        float b0 = bias ? bias[col] : 0.f;
        float b1 = bias ? bias[col + 1] : 0.f;
        out[ro0 + col]     = acc[nf][0] + b0;
        out[ro0 + col + 1] = acc[nf][1] + b1;
        out[ro1 + col]     = acc[nf][2] + b0;
        out[ro1 + col + 1] = acc[nf][3] + b1;
    }
}

// ---------------- scores, K-split 2: grid(32, 64), 256 thr ------------------
__global__ __launch_bounds__(256) void scores_kernel(
    const float* __restrict__ Va, const float* __restrict__ ba)
{
    int b = blockIdx.y;
    int kh = blockIdx.x & 1, sb = blockIdx.x >> 1;
    __shared__ float shwa[256], sva[256];
    int tid = threadIdx.x;
    if (tid < 256) {
        shwa[tid] = g_hwagh[b * 2048 + kh * 256 + tid] + ba[kh * 256 + tid];
        sva[tid]  = Va[kh * 256 + tid];
    }
    __syncthreads();
    int warp = tid >> 5, lane = tid & 31;
    int s = sb * 8 + warp;
    const float* uk = g_Uk + ((size_t)b * Sc + s) * Hc + kh * 256;
    float acc = 0.f;
#pragma unroll
    for (int j = 0; j < 2; j++) {
        int k = j * 128 + lane * 4;
        float4 u  = *(const float4*)(uk + k);
        float4 wv = *(const float4*)(shwa + k);
        float4 vv = *(const float4*)(sva + k);
        acc += tanhf(wv.x + u.x) * vv.x + tanhf(wv.y + u.y) * vv.y
             + tanhf(wv.z + u.z) * vv.z + tanhf(wv.w + u.w) * vv.w;
    }
#pragma unroll
    for (int o = 16; o; o >>= 1) acc += __shfl_xor_sync(0xffffffffu, acc, o);
    if (!lane) g_s2[kh * (Bc * Sc) + b * Sc + s] = acc;   // bv cancels in softmax
}

// ---------------- softmax over S=128 ----------------------------------------
__global__ void softmaxw_kernel(float* __restrict__ att_out, int t)
{
    int b = blockIdx.x, tid = threadIdx.x;   // 128 threads
    __shared__ float sw[Sc];
    sw[tid] = g_s2[b * Sc + tid] + g_s2[Bc * Sc + b * Sc + tid];
    __syncthreads();
    if (tid < 32) {
        float v0 = sw[tid], v1 = sw[tid + 32], v2 = sw[tid + 64], v3 = sw[tid + 96];
        float m = fmaxf(fmaxf(v0, v1), fmaxf(v2, v3));
#pragma unroll
        for (int o = 16; o; o >>= 1) m = fmaxf(m, __shfl_xor_sync(0xffffffffu, m, o));
        float e0 = expf(v0 - m), e1 = expf(v1 - m), e2 = expf(v2 - m), e3 = expf(v3 - m);
        float s = e0 + e1 + e2 + e3;
#pragma unroll
        for (int o = 16; o; o >>= 1) s += __shfl_xor_sync(0xffffffffu, s, o);
        float inv = 1.0f / s;
        sw[tid] = e0 * inv; sw[tid + 32] = e1 * inv;
        sw[tid + 64] = e2 * inv; sw[tid + 96] = e3 * inv;
    }
    __syncthreads();
    float w = sw[tid];
    g_w[b * Sc + tid] = w;
    att_out[((size_t)b * Tc + t) * Sc + tid] = w;
}

// ---------------- ctx[b][col] = sum_s w[s]*enc[b][s][col] -> bf16 hi/lo ------
__global__ void ctx_kernel(const float* __restrict__ enc)
{
    int b = blockIdx.y, col = blockIdx.x * 128 + threadIdx.x;
    __shared__ float w[Sc];
    w[threadIdx.x] = g_w[b * Sc + threadIdx.x];
    __syncthreads();
    const float* encb = enc + (size_t)b * Sc * Hc + col;
    float acc = 0.f;
#pragma unroll 8
    for (int s = 0; s < Sc; s++) acc += w[s] * encb[(size_t)s * Hc];
    split2(acc, g_ctxH + b * Hc + col, g_ctxL + b * Hc + col);
}

// ---------------- GRU gates ---------------------------------------------------
__global__ void gates_kernel(const float* __restrict__ b_ih, const float* __restrict__ b_hh, int t)
{
    int b = blockIdx.x, j = threadIdx.x;
    size_t r = (size_t)t * Bc + b;
    const float* giE = g_giE + r * (3 * Hc);
    const float* giC = g_giC + b * (3 * Hc);
    const float* gh  = g_hwagh + b * 2048 + 512;
    float rr = sigm(giE[j] + giC[j] + b_ih[j] + gh[j] + b_hh[j]);
    float z  = sigm(giE[Hc + j] + giC[Hc + j] + b_ih[Hc + j] + gh[Hc + j] + b_hh[Hc + j]);
    float n  = tanhf(giE[2 * Hc + j] + giC[2 * Hc + j] + b_ih[2 * Hc + j]
                     + rr * (gh[2 * Hc + j] + b_hh[2 * Hc + j]));
    float hp = g_h[b * Hc + j];
    float hn = (1.0f - z) * n + z * hp;
    g_h[b * Hc + j] = hn;
    split2(hn, g_hhi + b * Hc + j, g_hlo + b * Hc + j);
    split2(hn, g_hallH + r * Hc + j, g_hallL + r * Hc + j);
}

// ---------------- online log_softmax over V, one block per (b,t) row ---------
__global__ __launch_bounds__(512) void lsm_kernel(float* __restrict__ base)
{
    float* row = base + (size_t)blockIdx.x * Vc;
    __shared__ float redm[16], reds[16];
    int tid = threadIdx.x, lane = tid & 31, w = tid >> 5;

    float m = -3.4e38f, s = 0.f;
    for (int v = tid; v < Vc; v += 512) {
        float x = row[v];
        float nm = fmaxf(m, x);
        s = s * __expf(m - nm) + __expf(x - nm);
        m = nm;
    }
#pragma unroll
    for (int o = 16; o; o >>= 1) {
        float om = __shfl_xor_sync(0xffffffffu, m, o);
        float os = __shfl_xor_sync(0xffffffffu, s, o);
        float nm = fmaxf(m, om);
        s = s * __expf(m - nm) + os * __expf(om - nm);
        m = nm;
    }
    if (!lane) { redm[w] = m; reds[w] = s; }
    __syncthreads();
    float M = redm[0], S = reds[0];
#pragma unroll
    for (int i = 1; i < 16; i++) {
        float nm = fmaxf(M, redm[i]);
        S = S * __expf(M - nm) + reds[i] * __expf(redm[i] - nm);
        M = nm;
    }
    float ls = M + logf(S);
    for (int v = tid; v < Vc; v += 512) row[v] -= ls;
}

// ---------------- launch ----------------
extern "C" void kernel_launch(void* const* d_in, const int* in_sizes, int n_in,
                              void* d_out, int out_size)
{
    const float* enc  = (const float*)d_in[0];
    const float* h0   = (const float*)d_in[1];
    const int*   tgt  = (const int*)d_in[2];
    const float* emb  = (const float*)d_in[3];
    const float* Wa   = (const float*)d_in[4];
    const float* ba   = (const float*)d_in[5];
    const float* Ua   = (const float*)d_in[6];
    const float* bu   = (const float*)d_in[7];
    const float* Va   = (const float*)d_in[8];
    /* d_in[9] = bv : cancels inside softmax, never observable */
    const float* W_ih = (const float*)d_in[10];
    const float* W_hh = (const float*)d_in[11];
    const float* b_ih = (const float*)d_in[12];
    const float* b_hh = (const float*)d_in[13];
    const float* Wout = (const float*)d_in[14];
    const float* bout = (const float*)d_in[15];

    float* out  = (float*)d_out;
    float* logp = out;                                    // [B,T,V]
    float* hf   = out + (size_t)Bc * Tc * Vc;             // [1,B,H]
    float* att  = hf + (size_t)Bc * Hc;                   // [B,T,S]

    void *p_WoutH, *p_WoutL, *p_BcatH, *p_BcatL, *p_WihEH, *p_WihEL, *p_WihCH, *p_WihCL;
    void *p_UaTH, *p_UaTL, *p_encH, *p_encL, *p_hhi, *p_hlo, *p_xeH, *p_xeL;
    void *p_ctxH, *p_ctxL, *p_hallH, *p_hallL, *p_Uk, *p_hwagh, *p_giC, *p_giE;
    cudaGetSymbolAddress(&p_WoutH, g_WoutH); cudaGetSymbolAddress(&p_WoutL, g_WoutL);
    cudaGetSymbolAddress(&p_BcatH, g_BcatH); cudaGetSymbolAddress(&p_BcatL, g_BcatL);
    cudaGetSymbolAddress(&p_WihEH, g_WihEH); cudaGetSymbolAddress(&p_WihEL, g_WihEL);
    cudaGetSymbolAddress(&p_WihCH, g_WihCH); cudaGetSymbolAddress(&p_WihCL, g_WihCL);
    cudaGetSymbolAddress(&p_UaTH, g_UaTH);   cudaGetSymbolAddress(&p_UaTL, g_UaTL);
    cudaGetSymbolAddress(&p_encH, g_encH);   cudaGetSymbolAddress(&p_encL, g_encL);
    cudaGetSymbolAddress(&p_hhi, g_hhi);     cudaGetSymbolAddress(&p_hlo, g_hlo);
    cudaGetSymbolAddress(&p_xeH, g_xeH);     cudaGetSymbolAddress(&p_xeL, g_xeL);
    cudaGetSymbolAddress(&p_ctxH, g_ctxH);   cudaGetSymbolAddress(&p_ctxL, g_ctxL);
    cudaGetSymbolAddress(&p_hallH, g_hallH); cudaGetSymbolAddress(&p_hallL, g_hallL);
    cudaGetSymbolAddress(&p_Uk, g_Uk);       cudaGetSymbolAddress(&p_hwagh, g_hwagh);
    cudaGetSymbolAddress(&p_giC, g_giC);     cudaGetSymbolAddress(&p_giE, g_giE);

    // ---- setup conversions ----
    split_kernel<<<(Vc * Hc) / 1024, 256>>>(Wout, (bf16*)p_WoutH, (bf16*)p_WoutL, Vc * Hc);
    // Bcat rows 512..2047 = W_hh
    split_kernel<<<(3 * Hc * Hc) / 1024, 256>>>(W_hh, (bf16*)p_BcatH + 512 * Hc,
                                                (bf16*)p_BcatL + 512 * Hc, 3 * Hc * Hc);
    // Bcat rows 0..511 = Wa^T
    splitT_kernel<<<(Hc * Hc) / 256, 256>>>(Wa, (bf16*)p_BcatH, (bf16*)p_BcatL);
    splitT_kernel<<<(Hc * Hc) / 256, 256>>>(Ua, (bf16*)p_UaTH, (bf16*)p_UaTL);
    splitWih_kernel<<<(3 * Hc * Hc) / 256, 256>>>(W_ih);
    split_kernel<<<(Bc * Sc * Hc) / 1024, 256>>>(enc, (bf16*)p_encH, (bf16*)p_encL, Bc * Sc * Hc);

    inith_kernel<<<(Bc * Hc + 255) / 256, 256>>>(h0);
    xe_kernel<<<dim3(Tc, Bc), 128>>>(emb, tgt);

    // Uk = enc @ Ua^T' + bu : M=8192, N=512, K=512
    mma_nt_kernel<<<dim3(4, 128), 256>>>((bf16*)p_encH, (bf16*)p_encL,
                                         (bf16*)p_UaTH, (bf16*)p_UaTL,
                                         bu, (float*)p_Uk, Hc, (size_t)Hc, 0);
    // giE = xe @ WihE^T : M=4096, N=1536, K=512 (all steps, off critical path)
    mma_nt_kernel<<<dim3(12, 64), 256>>>((bf16*)p_xeH, (bf16*)p_xeL,
                                         (bf16*)p_WihEH, (bf16*)p_WihEL,
                                         nullptr, (float*)p_giE, Hc, (size_t)(3 * Hc), 0);

    for (int t = 0; t < Tc; t++) {
        // [hwa | gh] = h @ [WaT | W_hh]^T : N=2048
        mma_nt_kernel<<<dim3(16, 1), 256>>>((bf16*)p_hhi, (bf16*)p_hlo,
                                            (bf16*)p_BcatH, (bf16*)p_BcatL,
                                            nullptr, (float*)p_hwagh, Hc, (size_t)2048, 0);
        scores_kernel<<<dim3(32, Bc), 256>>>(Va, ba);
        softmaxw_kernel<<<Bc, 128>>>(att, t);
        ctx_kernel<<<dim3(4, Bc), 128>>>(enc);
        // giC = ctx @ WihC^T : N=1536, K=512
        mma_nt_kernel<<<dim3(12, 1), 256>>>((bf16*)p_ctxH, (bf16*)p_ctxL,
                                            (bf16*)p_WihCH, (bf16*)p_WihCL,
                                            nullptr, (float*)p_giC, Hc, (size_t)(3 * Hc), 0);
        gates_kernel<<<Bc, Hc>>>(b_ih, b_hh, t);
    }

    // logits for ALL steps: [4096, 32000] = h_all @ Wout^T + bout, scattered to [B,T,V]
    mma_nt_kernel<<<dim3(Vc / 128, 64), 256>>>((bf16*)p_hallH, (bf16*)p_hallL,
                                               (bf16*)p_WoutH, (bf16*)p_WoutL,
                                               bout, logp, Hc, 0, 1);
    lsm_kernel<<<Bc * Tc, 512>>>(logp);

    final_h_kernel<<<(Bc * Hc + 255) / 256, 256>>>(hf);
}

// round 7
// speedup vs baseline: 5.6267x; 1.3875x over previous
#include <cuda_runtime.h>
#include <cuda_bf16.h>
#include <math.h>
#include <stdint.h>

#define Bc 64
#define Sc 128
#define Tc 64
#define Hc 512
#define Vc 32000

typedef __nv_bfloat16 bf16;

// ---------------- scratch (device globals: no allocs allowed) ----------------
__device__ __align__(16) float g_Uk[(size_t)Bc * Sc * Hc];       // 16 MB
__device__ __align__(16) float g_h[Bc * Hc];
__device__ __align__(16) bf16  g_hhi[Bc * Hc], g_hlo[Bc * Hc];
__device__ __align__(16) float g_A4[4 * Bc * 2048];              // K-split partials [hwa|gh]
__device__ __align__(16) float g_giC4[4 * Bc * 1536];            // K-split partials giC
__device__ __align__(16) float g_s2[2 * Bc * Sc];                // score K-half partials
__device__ __align__(16) float g_giE[(size_t)Tc * Bc * 3 * Hc];  // 25 MB
__device__ __align__(16) bf16  g_xeH[(size_t)Tc * Bc * Hc], g_xeL[(size_t)Tc * Bc * Hc];
__device__ __align__(16) bf16  g_ctxH[Bc * Hc], g_ctxL[Bc * Hc];
__device__ __align__(16) bf16  g_hallH[(size_t)Tc * Bc * Hc], g_hallL[(size_t)Tc * Bc * Hc];
__device__ __align__(16) bf16  g_WoutH[(size_t)Vc * Hc], g_WoutL[(size_t)Vc * Hc];
__device__ __align__(16) bf16  g_BcatH[2048 * Hc], g_BcatL[2048 * Hc]; // [WaT|W_hh]
__device__ __align__(16) bf16  g_WihEH[3 * Hc * Hc], g_WihEL[3 * Hc * Hc];
__device__ __align__(16) bf16  g_WihCH[3 * Hc * Hc], g_WihCL[3 * Hc * Hc];
__device__ __align__(16) bf16  g_UaTH[Hc * Hc], g_UaTL[Hc * Hc];
__device__ __align__(16) bf16  g_encH[(size_t)Bc * Sc * Hc], g_encL[(size_t)Bc * Sc * Hc];

__device__ __forceinline__ float sigm(float x) { return 1.0f / (1.0f + expf(-x)); }
__device__ __forceinline__ float fast_tanh(float x) {
    float y; asm("tanh.approx.f32 %0, %1;" : "=f"(y) : "f"(x)); return y;
}
__device__ __forceinline__ void split2(float x, bf16* hi, bf16* lo) {
    bf16 h = __float2bfloat16(x);
    *hi = h;
    *lo = __float2bfloat16(x - __bfloat162float(h));
}

// ---------------- conversion kernels ----------------
__global__ void split_kernel(const float* __restrict__ src, bf16* __restrict__ hi,
                             bf16* __restrict__ lo, int n)
{
    int i = (blockIdx.x * 256 + threadIdx.x) * 4;
    if (i >= n) return;
    float4 v = *(const float4*)(src + i);
    split2(v.x, hi + i + 0, lo + i + 0);
    split2(v.y, hi + i + 1, lo + i + 1);
    split2(v.z, hi + i + 2, lo + i + 2);
    split2(v.w, hi + i + 3, lo + i + 3);
}

__global__ void splitT_kernel(const float* __restrict__ src, bf16* __restrict__ hi,
                              bf16* __restrict__ lo)
{
    int idx = blockIdx.x * 256 + threadIdx.x;
    int k = idx >> 9, n = idx & 511;
    split2(src[idx], hi + n * Hc + k, lo + n * Hc + k);
}

__global__ void splitWih_kernel(const float* __restrict__ W)
{
    int idx = blockIdx.x * 256 + threadIdx.x;   // over 1536*512
    int r = idx >> 9, c = idx & 511;
    split2(W[(size_t)r * 1024 + c], g_WihEH + idx, g_WihEL + idx);
    split2(W[(size_t)r * 1024 + 512 + c], g_WihCH + idx, g_WihCL + idx);
}

__global__ void inith_kernel(const float* __restrict__ h0) {
    int i = blockIdx.x * 256 + threadIdx.x;
    if (i < Bc * Hc) {
        float v = h0[i];
        g_h[i] = v;
        split2(v, g_hhi + i, g_hlo + i);
    }
}
__global__ void final_h_kernel(float* __restrict__ dst) {
    int i = blockIdx.x * 256 + threadIdx.x;
    if (i < Bc * Hc) dst[i] = g_h[i];
}

__global__ void xe_kernel(const float* __restrict__ emb, const int* __restrict__ tgt) {
    int t = blockIdx.x, b = blockIdx.y;
    int tok = (t == 0) ? 0 : tgt[b * Tc + t - 1];
    size_t base = ((size_t)t * Bc + b) * Hc;
    const float* e = emb + (size_t)tok * Hc;
    for (int k = threadIdx.x; k < Hc; k += 128)
        split2(e[k], g_xeH + base + k, g_xeL + base + k);
}

// ---------------- pipelined split-bf16 NT MMA ---------------------------------
// out[M,N] = A[M,K=512-rows] @ B[N,512-rows]^T ; lda/ldb fixed at 512.
// gridDim.z = K-split count; block z handles k in [z*Kcp, z*Kcp+Kcp), writes
// to out + z*pstride. 2-stage cp.async pipeline, KC=16 per iteration.
// scatter==1: row m -> ((m&63)*Tc + (m>>6))*Vc   (logits -> [B,T,V])
#define KC 16
#define LDApad 24
#define OFF_AH 0
#define OFF_AL (64 * LDApad)
#define OFF_BH (128 * LDApad)
#define OFF_BL (256 * LDApad)
#define STG_ELEMS (384 * LDApad)

#define MMA_BF16(c, a, b0_, b1_)                                           \
    asm volatile(                                                          \
        "mma.sync.aligned.m16n8k16.row.col.f32.bf16.bf16.f32 "             \
        "{%0,%1,%2,%3},{%4,%5,%6,%7},{%8,%9},{%0,%1,%2,%3};"               \
        : "+f"(c[0]), "+f"(c[1]), "+f"(c[2]), "+f"(c[3])                   \
        : "r"(a[0]), "r"(a[1]), "r"(a[2]), "r"(a[3]), "r"(b0_), "r"(b1_))

__device__ __forceinline__ void cpa16(uint32_t dst, const void* src) {
    asm volatile("cp.async.ca.shared.global [%0], [%1], 16;" :: "r"(dst), "l"(src));
}

__global__ __launch_bounds__(256) void mma_nt_kernel(
    const bf16* __restrict__ Ahi, const bf16* __restrict__ Alo,
    const bf16* __restrict__ Bhi, const bf16* __restrict__ Blo,
    const float* __restrict__ bias, float* __restrict__ out,
    int Kcp, size_t ldc, int scatter, size_t pstride)
{
    __shared__ __align__(16) bf16 sm[2 * STG_ELEMS];
    uint32_t sb = (uint32_t)__cvta_generic_to_shared(sm);

    int tid = threadIdx.x, lane = tid & 31, wid = tid >> 5;
    int g = lane >> 2, t4 = lane & 3;
    int wy = wid & 3, wx = wid >> 2;
    int m0 = blockIdx.y * 64, n0 = blockIdx.x * 128;
    int kb = blockIdx.z * Kcp;
    out += blockIdx.z * pstride;

    // per-thread load assignments
    int ac = tid & 127, arow = ac >> 1, ao8 = (ac & 1) * 8;   // A chunk
    const bf16* aptr = (tid < 128 ? Ahi : Alo) + (size_t)(m0 + arow) * 512 + ao8;
    uint32_t adst = sb + 2 * ((tid < 128 ? OFF_AH : OFF_AL) + arow * LDApad + ao8);
    int brow = tid >> 1, bo8 = (tid & 1) * 8;                  // B chunks (H and L)
    const bf16* bhp = Bhi + (size_t)(n0 + brow) * 512 + bo8;
    const bf16* blp = Blo + (size_t)(n0 + brow) * 512 + bo8;
    uint32_t bhd = sb + 2 * (OFF_BH + brow * LDApad + bo8);
    uint32_t bld = sb + 2 * (OFF_BL + brow * LDApad + bo8);

    int niters = Kcp / KC;
    float acc[8][4] = {};

    // prologue: stage 0 <- k = kb
    cpa16(adst, aptr + kb);
    cpa16(bhd, bhp + kb);
    cpa16(bld, blp + kb);
    asm volatile("cp.async.commit_group;");

    int st = 0;
    for (int it = 0; it < niters; it++) {
        if (it + 1 < niters) {
            int kn = kb + (it + 1) * KC;
            uint32_t so = (uint32_t)((st ^ 1) * STG_ELEMS * 2);
            cpa16(adst + so, aptr + kn);
            cpa16(bhd + so, bhp + kn);
            cpa16(bld + so, blp + kn);
            asm volatile("cp.async.commit_group;");
            asm volatile("cp.async.wait_group 1;");
        } else {
            asm volatile("cp.async.wait_group 0;");
        }
        __syncthreads();

        const bf16* base = sm + st * STG_ELEMS;
        int ar = (wy * 16 + g) * LDApad + t4 * 2;
        uint32_t aH[4], aL[4];
        aH[0] = *(const uint32_t*)&base[OFF_AH + ar];
        aH[1] = *(const uint32_t*)&base[OFF_AH + ar + 8 * LDApad];
        aH[2] = *(const uint32_t*)&base[OFF_AH + ar + 8];
        aH[3] = *(const uint32_t*)&base[OFF_AH + ar + 8 * LDApad + 8];
        aL[0] = *(const uint32_t*)&base[OFF_AL + ar];
        aL[1] = *(const uint32_t*)&base[OFF_AL + ar + 8 * LDApad];
        aL[2] = *(const uint32_t*)&base[OFF_AL + ar + 8];
        aL[3] = *(const uint32_t*)&base[OFF_AL + ar + 8 * LDApad + 8];
#pragma unroll
        for (int nf = 0; nf < 8; nf++) {
            int br = (wx * 64 + nf * 8 + g) * LDApad + t4 * 2;
            uint32_t bH0 = *(const uint32_t*)&base[OFF_BH + br];
            uint32_t bH1 = *(const uint32_t*)&base[OFF_BH + br + 8];
            uint32_t bL0 = *(const uint32_t*)&base[OFF_BL + br];
            uint32_t bL1 = *(const uint32_t*)&base[OFF_BL + br + 8];
            MMA_BF16(acc[nf], aH, bH0, bH1);
            MMA_BF16(acc[nf], aH, bL0, bL1);
            MMA_BF16(acc[nf], aL, bH0, bH1);
        }
        __syncthreads();
        st ^= 1;
    }

    int mr0 = m0 + wy * 16 + g, mr1 = mr0 + 8;
    size_t ro0, ro1;
    if (scatter) {
        ro0 = ((size_t)(mr0 & 63) * Tc + (mr0 >> 6)) * Vc;
        ro1 = ((size_t)(mr1 & 63) * Tc + (mr1 >> 6)) * Vc;
    } else {
        ro0 = (size_t)mr0 * ldc;
        ro1 = (size_t)mr1 * ldc;
    }
#pragma unroll
    for (int nf = 0; nf < 8; nf++) {
        int col = n0 + wx * 64 + nf * 8 + t4 * 2;
        float b0 = bias ? bias[col] : 0.f;
        float b1 = bias ? bias[col + 1] : 0.f;
        out[ro0 + col]     = acc[nf][0] + b0;
        out[ro0 + col + 1] = acc[nf][1] + b1;
        out[ro1 + col]     = acc[nf][2] + b0;
        out[ro1 + col + 1] = acc[nf][3] + b1;
    }
}

// ---------------- scores (sums 4 GEMM K-split partials of hwa) ---------------
__global__ __launch_bounds__(256) void scores_kernel(
    const float* __restrict__ Va, const float* __restrict__ ba)
{
    int b = blockIdx.y;
    int kh = blockIdx.x & 1, sb = blockIdx.x >> 1;
    __shared__ float shwa[256], sva[256];
    int tid = threadIdx.x;
    {
        int c = kh * 256 + tid;
        float v = ba[c];
#pragma unroll
        for (int p = 0; p < 4; p++) v += g_A4[(size_t)p * Bc * 2048 + b * 2048 + c];
        shwa[tid] = v;
        sva[tid]  = Va[c];
    }
    __syncthreads();
    int warp = tid >> 5, lane = tid & 31;
    int s = sb * 8 + warp;
    const float* uk = g_Uk + ((size_t)b * Sc + s) * Hc + kh * 256;
    float acc = 0.f;
#pragma unroll
    for (int j = 0; j < 2; j++) {
        int k = j * 128 + lane * 4;
        float4 u  = *(const float4*)(uk + k);
        float4 wv = *(const float4*)(shwa + k);
        float4 vv = *(const float4*)(sva + k);
        acc += fast_tanh(wv.x + u.x) * vv.x + fast_tanh(wv.y + u.y) * vv.y
             + fast_tanh(wv.z + u.z) * vv.z + fast_tanh(wv.w + u.w) * vv.w;
    }
#pragma unroll
    for (int o = 16; o; o >>= 1) acc += __shfl_xor_sync(0xffffffffu, acc, o);
    if (!lane) g_s2[kh * (Bc * Sc) + b * Sc + s] = acc;   // bv cancels in softmax
}

// ---------------- fused softmax + ctx: grid (4, 64), 128 thr ------------------
__global__ void ctxsm_kernel(const float* __restrict__ enc, float* __restrict__ att_out, int t)
{
    int b = blockIdx.y, cb = blockIdx.x, tid = threadIdx.x;
    __shared__ float sw[Sc];
    sw[tid] = g_s2[b * Sc + tid] + g_s2[Bc * Sc + b * Sc + tid];
    __syncthreads();
    if (tid < 32) {
        float v0 = sw[tid], v1 = sw[tid + 32], v2 = sw[tid + 64], v3 = sw[tid + 96];
        float m = fmaxf(fmaxf(v0, v1), fmaxf(v2, v3));
#pragma unroll
        for (int o = 16; o; o >>= 1) m = fmaxf(m, __shfl_xor_sync(0xffffffffu, m, o));
        float e0 = expf(v0 - m), e1 = expf(v1 - m), e2 = expf(v2 - m), e3 = expf(v3 - m);
        float s = e0 + e1 + e2 + e3;
#pragma unroll
        for (int o = 16; o; o >>= 1) s += __shfl_xor_sync(0xffffffffu, s, o);
        float inv = 1.0f / s;
        sw[tid] = e0 * inv; sw[tid + 32] = e1 * inv;
        sw[tid + 64] = e2 * inv; sw[tid + 96] = e3 * inv;
    }
    __syncthreads();
    if (cb == 0) att_out[((size_t)b * Tc + t) * Sc + tid] = sw[tid];

    int col = cb * 128 + tid;
    const float* encb = enc + (size_t)b * Sc * Hc + col;
    float acc = 0.f;
#pragma unroll 8
    for (int s = 0; s < Sc; s++) acc += sw[s] * encb[(size_t)s * Hc];
    split2(acc, g_ctxH + b * Hc + col, g_ctxL + b * Hc + col);
}

// ---------------- GRU gates (sums 4 K-split partials of gh and giC) ----------
__global__ void gates_kernel(const float* __restrict__ b_ih, const float* __restrict__ b_hh, int t)
{
    int b = blockIdx.x, j = threadIdx.x;   // 512 threads
    float ghr = 0.f, ghz = 0.f, ghn = 0.f, cr = 0.f, cz = 0.f, cn = 0.f;
#pragma unroll
    for (int p = 0; p < 4; p++) {
        const float* A4 = g_A4 + (size_t)p * Bc * 2048 + b * 2048 + 512;
        ghr += A4[j]; ghz += A4[Hc + j]; ghn += A4[2 * Hc + j];
        const float* C4 = g_giC4 + (size_t)p * Bc * 1536 + b * 1536;
        cr += C4[j]; cz += C4[Hc + j]; cn += C4[2 * Hc + j];
    }
    size_t r = (size_t)t * Bc + b;
    const float* giE = g_giE + r * (3 * Hc);
    float rr = sigm(giE[j] + cr + b_ih[j] + ghr + b_hh[j]);
    float z  = sigm(giE[Hc + j] + cz + b_ih[Hc + j] + ghz + b_hh[Hc + j]);
    float n  = tanhf(giE[2 * Hc + j] + cn + b_ih[2 * Hc + j] + rr * (ghn + b_hh[2 * Hc + j]));
    float hp = g_h[b * Hc + j];
    float hn = (1.0f - z) * n + z * hp;
    g_h[b * Hc + j] = hn;
    split2(hn, g_hhi + b * Hc + j, g_hlo + b * Hc + j);
    split2(hn, g_hallH + r * Hc + j, g_hallL + r * Hc + j);
}

// ---------------- online log_softmax over V, one block per (b,t) row ---------
__global__ __launch_bounds__(512) void lsm_kernel(float* __restrict__ base)
{
    float4* row = (float4*)(base + (size_t)blockIdx.x * Vc);
    const int NV4 = Vc / 4;
    __shared__ float redm[16], reds[16];
    int tid = threadIdx.x, lane = tid & 31, w = tid >> 5;

    float m = -3.4e38f, s = 0.f;
    for (int v = tid; v < NV4; v += 512) {
        float4 x = row[v];
        float lm = fmaxf(fmaxf(x.x, x.y), fmaxf(x.z, x.w));
        float nm = fmaxf(m, lm);
        s = s * __expf(m - nm) + __expf(x.x - nm) + __expf(x.y - nm)
            + __expf(x.z - nm) + __expf(x.w - nm);
        m = nm;
    }
#pragma unroll
    for (int o = 16; o; o >>= 1) {
        float om = __shfl_xor_sync(0xffffffffu, m, o);
        float os = __shfl_xor_sync(0xffffffffu, s, o);
        float nm = fmaxf(m, om);
        s = s * __expf(m - nm) + os * __expf(om - nm);
        m = nm;
    }
    if (!lane) { redm[w] = m; reds[w] = s; }
    __syncthreads();
    float M = redm[0], S = reds[0];
#pragma unroll
    for (int i = 1; i < 16; i++) {
        float nm = fmaxf(M, redm[i]);
        S = S * __expf(M - nm) + reds[i] * __expf(redm[i] - nm);
        M = nm;
    }
    float ls = M + logf(S);
    for (int v = tid; v < NV4; v += 512) {
        float4 x = row[v];
        x.x -= ls; x.y -= ls; x.z -= ls; x.w -= ls;
        row[v] = x;
    }
}

// ---------------- launch ----------------
extern "C" void kernel_launch(void* const* d_in, const int* in_sizes, int n_in,
                              void* d_out, int out_size)
{
    const float* enc  = (const float*)d_in[0];
    const float* h0   = (const float*)d_in[1];
    const int*   tgt  = (const int*)d_in[2];
    const float* emb  = (const float*)d_in[3];
    const float* Wa   = (const float*)d_in[4];
    const float* ba   = (const float*)d_in[5];
    const float* Ua   = (const float*)d_in[6];
    const float* bu   = (const float*)d_in[7];
    const float* Va   = (const float*)d_in[8];
    /* d_in[9] = bv : cancels inside softmax, never observable */
    const float* W_ih = (const float*)d_in[10];
    const float* W_hh = (const float*)d_in[11];
    const float* b_ih = (const float*)d_in[12];
    const float* b_hh = (const float*)d_in[13];
    const float* Wout = (const float*)d_in[14];
    const float* bout = (const float*)d_in[15];

    float* out  = (float*)d_out;
    float* logp = out;                                    // [B,T,V]
    float* hf   = out + (size_t)Bc * Tc * Vc;             // [1,B,H]
    float* att  = hf + (size_t)Bc * Hc;                   // [B,T,S]

    void *p_WoutH, *p_WoutL, *p_BcatH, *p_BcatL, *p_WihEH, *p_WihEL, *p_WihCH, *p_WihCL;
    void *p_UaTH, *p_UaTL, *p_encH, *p_encL, *p_hhi, *p_hlo, *p_xeH, *p_xeL;
    void *p_ctxH, *p_ctxL, *p_hallH, *p_hallL, *p_Uk, *p_A4, *p_giC4, *p_giE;
    cudaGetSymbolAddress(&p_WoutH, g_WoutH); cudaGetSymbolAddress(&p_WoutL, g_WoutL);
    cudaGetSymbolAddress(&p_BcatH, g_BcatH); cudaGetSymbolAddress(&p_BcatL, g_BcatL);
    cudaGetSymbolAddress(&p_WihEH, g_WihEH); cudaGetSymbolAddress(&p_WihEL, g_WihEL);
    cudaGetSymbolAddress(&p_WihCH, g_WihCH); cudaGetSymbolAddress(&p_WihCL, g_WihCL);
    cudaGetSymbolAddress(&p_UaTH, g_UaTH);   cudaGetSymbolAddress(&p_UaTL, g_UaTL);
    cudaGetSymbolAddress(&p_encH, g_encH);   cudaGetSymbolAddress(&p_encL, g_encL);
    cudaGetSymbolAddress(&p_hhi, g_hhi);     cudaGetSymbolAddress(&p_hlo, g_hlo);
    cudaGetSymbolAddress(&p_xeH, g_xeH);     cudaGetSymbolAddress(&p_xeL, g_xeL);
    cudaGetSymbolAddress(&p_ctxH, g_ctxH);   cudaGetSymbolAddress(&p_ctxL, g_ctxL);
    cudaGetSymbolAddress(&p_hallH, g_hallH); cudaGetSymbolAddress(&p_hallL, g_hallL);
    cudaGetSymbolAddress(&p_Uk, g_Uk);       cudaGetSymbolAddress(&p_A4, g_A4);
    cudaGetSymbolAddress(&p_giC4, g_giC4);   cudaGetSymbolAddress(&p_giE, g_giE);

    // ---- setup conversions ----
    split_kernel<<<(Vc * Hc) / 1024, 256>>>(Wout, (bf16*)p_WoutH, (bf16*)p_WoutL, Vc * Hc);
    split_kernel<<<(3 * Hc * Hc) / 1024, 256>>>(W_hh, (bf16*)p_BcatH + 512 * Hc,
                                                (bf16*)p_BcatL + 512 * Hc, 3 * Hc * Hc);
    splitT_kernel<<<(Hc * Hc) / 256, 256>>>(Wa, (bf16*)p_BcatH, (bf16*)p_BcatL);
    splitT_kernel<<<(Hc * Hc) / 256, 256>>>(Ua, (bf16*)p_UaTH, (bf16*)p_UaTL);
    splitWih_kernel<<<(3 * Hc * Hc) / 256, 256>>>(W_ih);
    split_kernel<<<(Bc * Sc * Hc) / 1024, 256>>>(enc, (bf16*)p_encH, (bf16*)p_encL, Bc * Sc * Hc);

    inith_kernel<<<(Bc * Hc + 255) / 256, 256>>>(h0);
    xe_kernel<<<dim3(Tc, Bc), 128>>>(emb, tgt);

    // Uk = enc @ UaT^T + bu : M=8192, N=512, K=512
    mma_nt_kernel<<<dim3(4, 128, 1), 256>>>((bf16*)p_encH, (bf16*)p_encL,
                                            (bf16*)p_UaTH, (bf16*)p_UaTL,
                                            bu, (float*)p_Uk, Hc, (size_t)Hc, 0, 0);
    // giE = xe @ WihE^T : M=4096, N=1536, K=512
    mma_nt_kernel<<<dim3(12, 64, 1), 256>>>((bf16*)p_xeH, (bf16*)p_xeL,
                                            (bf16*)p_WihEH, (bf16*)p_WihEL,
                                            nullptr, (float*)p_giE, Hc, (size_t)(3 * Hc), 0, 0);

    for (int t = 0; t < Tc; t++) {
        // [hwa | gh] partials = h @ Bcat^T : N=2048, K-split 4
        mma_nt_kernel<<<dim3(16, 1, 4), 256>>>((bf16*)p_hhi, (bf16*)p_hlo,
                                               (bf16*)p_BcatH, (bf16*)p_BcatL,
                                               nullptr, (float*)p_A4, 128, (size_t)2048,
                                               0, (size_t)Bc * 2048);
        scores_kernel<<<dim3(32, Bc), 256>>>(Va, ba);
        ctxsm_kernel<<<dim3(4, Bc), 128>>>(enc, att, t);
        // giC partials = ctx @ WihC^T : N=1536, K-split 4
        mma_nt_kernel<<<dim3(12, 1, 4), 256>>>((bf16*)p_ctxH, (bf16*)p_ctxL,
                                               (bf16*)p_WihCH, (bf16*)p_WihCL,
                                               nullptr, (float*)p_giC4, 128, (size_t)1536,
                                               0, (size_t)Bc * 1536);
        gates_kernel<<<Bc, Hc>>>(b_ih, b_hh, t);
    }

    // logits for ALL steps: [4096, 32000] = h_all @ Wout^T + bout -> [B,T,V]
    mma_nt_kernel<<<dim3(Vc / 128, 64, 1), 256>>>((bf16*)p_hallH, (bf16*)p_hallL,
                                                  (bf16*)p_WoutH, (bf16*)p_WoutL,
                                                  bout, logp, Hc, 0, 1, 0);
    lsm_kernel<<<Bc * Tc, 512>>>(logp);

    final_h_kernel<<<(Bc * Hc + 255) / 256, 256>>>(hf);
}

// round 8
// speedup vs baseline: 5.8341x; 1.0369x over previous
#include <cuda_runtime.h>
#include <cuda_bf16.h>
#include <math.h>
#include <stdint.h>

#define Bc 64
#define Sc 128
#define Tc 64
#define Hc 512
#define Vc 32000
#define NBLK 64

typedef __nv_bfloat16 bf16;

// ---------------- scratch (device globals: no allocs allowed) ----------------
__device__ __align__(16) float g_Uk[(size_t)Bc * Sc * Hc];       // 16 MB
__device__ __align__(16) float g_h[Bc * Hc];
__device__ __align__(16) bf16  g_hhi[Bc * Hc], g_hlo[Bc * Hc];
__device__ __align__(16) float g_A4[4 * Bc * 2048];              // K-split partials [hwa|gh]
__device__ __align__(16) float g_giC4[4 * Bc * 1536];            // K-split partials giC
__device__ __align__(16) float g_giE[(size_t)Tc * Bc * 3 * Hc];  // 25 MB
__device__ __align__(16) bf16  g_xeH[(size_t)Tc * Bc * Hc], g_xeL[(size_t)Tc * Bc * Hc];
__device__ __align__(16) bf16  g_ctxH[Bc * Hc], g_ctxL[Bc * Hc];
__device__ __align__(16) bf16  g_hallH[(size_t)Tc * Bc * Hc], g_hallL[(size_t)Tc * Bc * Hc];
__device__ __align__(16) bf16  g_WoutH[(size_t)Vc * Hc], g_WoutL[(size_t)Vc * Hc];
__device__ __align__(16) bf16  g_BcatH[2048 * Hc], g_BcatL[2048 * Hc]; // [WaT|W_hh]
__device__ __align__(16) bf16  g_WihEH[3 * Hc * Hc], g_WihEL[3 * Hc * Hc];
__device__ __align__(16) bf16  g_WihCH[3 * Hc * Hc], g_WihCL[3 * Hc * Hc];
__device__ __align__(16) bf16  g_UaTH[Hc * Hc], g_UaTL[Hc * Hc];
__device__ __align__(16) bf16  g_encH[(size_t)Bc * Sc * Hc], g_encL[(size_t)Bc * Sc * Hc];
__device__ int g_barrier;

__device__ __forceinline__ float sigm(float x) { return 1.0f / (1.0f + expf(-x)); }
__device__ __forceinline__ float fast_tanh(float x) {
    float y; asm("tanh.approx.f32 %0, %1;" : "=f"(y) : "f"(x)); return y;
}
__device__ __forceinline__ void split2(float x, bf16* hi, bf16* lo) {
    bf16 h = __float2bfloat16(x);
    *hi = h;
    *lo = __float2bfloat16(x - __bfloat162float(h));
}

// ---------------- conversion kernels ----------------
__global__ void split_kernel(const float* __restrict__ src, bf16* __restrict__ hi,
                             bf16* __restrict__ lo, int n)
{
    int i = (blockIdx.x * 256 + threadIdx.x) * 4;
    if (i >= n) return;
    float4 v = *(const float4*)(src + i);
    split2(v.x, hi + i + 0, lo + i + 0);
    split2(v.y, hi + i + 1, lo + i + 1);
    split2(v.z, hi + i + 2, lo + i + 2);
    split2(v.w, hi + i + 3, lo + i + 3);
}

__global__ void splitT_kernel(const float* __restrict__ src, bf16* __restrict__ hi,
                              bf16* __restrict__ lo)
{
    int idx = blockIdx.x * 256 + threadIdx.x;
    int k = idx >> 9, n = idx & 511;
    split2(src[idx], hi + n * Hc + k, lo + n * Hc + k);
}

__global__ void splitWih_kernel(const float* __restrict__ W)
{
    int idx = blockIdx.x * 256 + threadIdx.x;   // over 1536*512
    int r = idx >> 9, c = idx & 511;
    split2(W[(size_t)r * 1024 + c], g_WihEH + idx, g_WihEL + idx);
    split2(W[(size_t)r * 1024 + 512 + c], g_WihCH + idx, g_WihCL + idx);
}

__global__ void inith_kernel(const float* __restrict__ h0) {
    int i = blockIdx.x * 256 + threadIdx.x;
    if (i == 0) g_barrier = 0;
    if (i < Bc * Hc) {
        float v = h0[i];
        g_h[i] = v;
        split2(v, g_hhi + i, g_hlo + i);
    }
}
__global__ void final_h_kernel(float* __restrict__ dst) {
    int i = blockIdx.x * 256 + threadIdx.x;
    if (i < Bc * Hc) dst[i] = g_h[i];
}

__global__ void xe_kernel(const float* __restrict__ emb, const int* __restrict__ tgt) {
    int t = blockIdx.x, b = blockIdx.y;
    int tok = (t == 0) ? 0 : tgt[b * Tc + t - 1];
    size_t base = ((size_t)t * Bc + b) * Hc;
    const float* e = emb + (size_t)tok * Hc;
    for (int k = threadIdx.x; k < Hc; k += 128)
        split2(e[k], g_xeH + base + k, g_xeL + base + k);
}

// ---------------- split-bf16 NT MMA tile (device fn) --------------------------
// 64(M) x 128(N) tile, KC=16 2-stage cp.async pipeline, lda/ldb = 512.
#define KC 16
#define LDApad 24
#define OFF_AH 0
#define OFF_AL (64 * LDApad)
#define OFF_BH (128 * LDApad)
#define OFF_BL (256 * LDApad)
#define STG_ELEMS (384 * LDApad)

#define MMA_BF16(c, a, b0_, b1_)                                           \
    asm volatile(                                                          \
        "mma.sync.aligned.m16n8k16.row.col.f32.bf16.bf16.f32 "             \
        "{%0,%1,%2,%3},{%4,%5,%6,%7},{%8,%9},{%0,%1,%2,%3};"               \
        : "+f"(c[0]), "+f"(c[1]), "+f"(c[2]), "+f"(c[3])                   \
        : "r"(a[0]), "r"(a[1]), "r"(a[2]), "r"(a[3]), "r"(b0_), "r"(b1_))

__device__ __forceinline__ void cpa16(uint32_t dst, const void* src) {
    asm volatile("cp.async.ca.shared.global [%0], [%1], 16;" :: "r"(dst), "l"(src));
}

__device__ __forceinline__ void mma_tile(
    bf16* sm, const bf16* Ahi, const bf16* Alo,
    const bf16* Bhi, const bf16* Blo,
    const float* bias, float* out,
    int m0, int n0, int kb, int niters, size_t ldc, int scatter, int nterms)
{
    uint32_t sb = (uint32_t)__cvta_generic_to_shared(sm);
    int tid = threadIdx.x, lane = tid & 31, wid = tid >> 5;
    int g = lane >> 2, t4 = lane & 3;
    int wy = wid & 3, wx = wid >> 2;

    int ac = tid & 127, arow = ac >> 1, ao8 = (ac & 1) * 8;
    const bf16* aptr = (tid < 128 ? Ahi : Alo) + (size_t)(m0 + arow) * 512 + ao8;
    uint32_t adst = sb + 2 * ((tid < 128 ? OFF_AH : OFF_AL) + arow * LDApad + ao8);
    int brow = tid >> 1, bo8 = (tid & 1) * 8;
    const bf16* bhp = Bhi + (size_t)(n0 + brow) * 512 + bo8;
    const bf16* blp = Blo + (size_t)(n0 + brow) * 512 + bo8;
    uint32_t bhd = sb + 2 * (OFF_BH + brow * LDApad + bo8);
    uint32_t bld = sb + 2 * (OFF_BL + brow * LDApad + bo8);

    float acc[8][4] = {};

    cpa16(adst, aptr + kb);
    cpa16(bhd, bhp + kb);
    cpa16(bld, blp + kb);
    asm volatile("cp.async.commit_group;");

    int st = 0;
    for (int it = 0; it < niters; it++) {
        if (it + 1 < niters) {
            int kn = kb + (it + 1) * KC;
            uint32_t so = (uint32_t)((st ^ 1) * STG_ELEMS * 2);
            cpa16(adst + so, aptr + kn);
            cpa16(bhd + so, bhp + kn);
            cpa16(bld + so, blp + kn);
            asm volatile("cp.async.commit_group;");
            asm volatile("cp.async.wait_group 1;");
        } else {
            asm volatile("cp.async.wait_group 0;");
        }
        __syncthreads();

        const bf16* base = sm + st * STG_ELEMS;
        int ar = (wy * 16 + g) * LDApad + t4 * 2;
        uint32_t aH[4], aL[4];
        aH[0] = *(const uint32_t*)&base[OFF_AH + ar];
        aH[1] = *(const uint32_t*)&base[OFF_AH + ar + 8 * LDApad];
        aH[2] = *(const uint32_t*)&base[OFF_AH + ar + 8];
        aH[3] = *(const uint32_t*)&base[OFF_AH + ar + 8 * LDApad + 8];
        aL[0] = *(const uint32_t*)&base[OFF_AL + ar];
        aL[1] = *(const uint32_t*)&base[OFF_AL + ar + 8 * LDApad];
        aL[2] = *(const uint32_t*)&base[OFF_AL + ar + 8];
        aL[3] = *(const uint32_t*)&base[OFF_AL + ar + 8 * LDApad + 8];
#pragma unroll
        for (int nf = 0; nf < 8; nf++) {
            int br = (wx * 64 + nf * 8 + g) * LDApad + t4 * 2;
            uint32_t bH0 = *(const uint32_t*)&base[OFF_BH + br];
            uint32_t bH1 = *(const uint32_t*)&base[OFF_BH + br + 8];
            uint32_t bL0 = *(const uint32_t*)&base[OFF_BL + br];
            uint32_t bL1 = *(const uint32_t*)&base[OFF_BL + br + 8];
            MMA_BF16(acc[nf], aH, bH0, bH1);
            MMA_BF16(acc[nf], aH, bL0, bL1);
            if (nterms == 3) MMA_BF16(acc[nf], aL, bH0, bH1);
        }
        __syncthreads();
        st ^= 1;
    }

    int mr0 = m0 + wy * 16 + g, mr1 = mr0 + 8;
    size_t ro0, ro1;
    if (scatter) {
        ro0 = ((size_t)(mr0 & 63) * Tc + (mr0 >> 6)) * Vc;
        ro1 = ((size_t)(mr1 & 63) * Tc + (mr1 >> 6)) * Vc;
    } else {
        ro0 = (size_t)mr0 * ldc;
        ro1 = (size_t)mr1 * ldc;
    }
#pragma unroll
    for (int nf = 0; nf < 8; nf++) {
        int col = n0 + wx * 64 + nf * 8 + t4 * 2;
        float b0 = bias ? bias[col] : 0.f;
        float b1 = bias ? bias[col + 1] : 0.f;
        out[ro0 + col]     = acc[nf][0] + b0;
        out[ro0 + col + 1] = acc[nf][1] + b1;
        out[ro1 + col]     = acc[nf][2] + b0;
        out[ro1 + col + 1] = acc[nf][3] + b1;
    }
}

// ---------------- standalone MMA kernel (setup + logits) ---------------------
__global__ __launch_bounds__(256) void mma_nt_kernel(
    const bf16* __restrict__ Ahi, const bf16* __restrict__ Alo,
    const bf16* __restrict__ Bhi, const bf16* __restrict__ Blo,
    const float* __restrict__ bias, float* __restrict__ out,
    int Kcp, size_t ldc, int scatter, int nterms)
{
    __shared__ __align__(16) bf16 sm[2 * STG_ELEMS];
    mma_tile(sm, Ahi, Alo, Bhi, Blo, bias, out,
             blockIdx.y * 64, blockIdx.x * 128, 0, Kcp / KC, ldc, scatter, nterms);
}

// ---------------- persistent loop kernel --------------------------------------
// 64 blocks x 256 threads; 4 phases per step, grid barrier between phases.
__global__ __launch_bounds__(256) void loop_kernel(
    const float* __restrict__ enc, const float* __restrict__ Va,
    const float* __restrict__ ba, const float* __restrict__ b_ih,
    const float* __restrict__ b_hh, float* __restrict__ att)
{
    __shared__ __align__(16) bf16 sm[2 * STG_ELEMS];   // 36.9 KB, reused by attn
    int bid = blockIdx.x, tid = threadIdx.x;
    int lane = tid & 31, warp = tid >> 5;
    int gen = 0;

    float* shwa = (float*)sm;          // 512
    float* sva  = shwa + 512;          // 512
    float* sw   = sva + 512;           // 128

#define GRID_BAR()                                                         \
    do {                                                                   \
        __syncthreads();                                                   \
        __threadfence();                                                   \
        gen += NBLK;                                                       \
        if (tid == 0) {                                                    \
            atomicAdd(&g_barrier, 1);                                      \
            while (atomicAdd(&g_barrier, 0) < gen) {}                      \
        }                                                                  \
        __syncthreads();                                                   \
    } while (0)

    for (int t = 0; t < Tc; t++) {
        // ---- phase 1: [hwa|gh] partials = h @ Bcat^T, 16 N-tiles x 4 K-splits
        {
            int n0 = (bid & 15) * 128, kz = bid >> 4;
            mma_tile(sm, g_hhi, g_hlo, g_BcatH, g_BcatL, nullptr,
                     g_A4 + (size_t)kz * Bc * 2048,
                     0, n0, kz * 128, 128 / KC, 2048, 0, 3);
        }
        GRID_BAR();

        // ---- phase 2: fused scores + softmax + ctx (block = batch row) ------
        {
            int b = bid;
            for (int i = tid; i < Hc; i += 256) {
                float v = ba[i];
#pragma unroll
                for (int p = 0; p < 4; p++) v += g_A4[(size_t)p * Bc * 2048 + b * 2048 + i];
                shwa[i] = v;
                sva[i] = Va[i];
            }
            __syncthreads();
            // scores: 8 warps x 16 s
#pragma unroll 2
            for (int si = 0; si < 16; si++) {
                int s = warp * 16 + si;
                const float* uk = g_Uk + ((size_t)b * Sc + s) * Hc;
                float acc = 0.f;
#pragma unroll
                for (int j = 0; j < 4; j++) {
                    int k = j * 128 + lane * 4;
                    float4 u  = *(const float4*)(uk + k);
                    float4 wv = *(const float4*)(shwa + k);
                    float4 vv = *(const float4*)(sva + k);
                    acc += fast_tanh(wv.x + u.x) * vv.x + fast_tanh(wv.y + u.y) * vv.y
                         + fast_tanh(wv.z + u.z) * vv.z + fast_tanh(wv.w + u.w) * vv.w;
                }
#pragma unroll
                for (int o = 16; o; o >>= 1) acc += __shfl_xor_sync(0xffffffffu, acc, o);
                if (!lane) sw[s] = acc;    // bv cancels in softmax
            }
            __syncthreads();
            if (warp == 0) {
                float v0 = sw[lane], v1 = sw[lane + 32], v2 = sw[lane + 64], v3 = sw[lane + 96];
                float m = fmaxf(fmaxf(v0, v1), fmaxf(v2, v3));
#pragma unroll
                for (int o = 16; o; o >>= 1) m = fmaxf(m, __shfl_xor_sync(0xffffffffu, m, o));
                float e0 = expf(v0 - m), e1 = expf(v1 - m), e2 = expf(v2 - m), e3 = expf(v3 - m);
                float s = e0 + e1 + e2 + e3;
#pragma unroll
                for (int o = 16; o; o >>= 1) s += __shfl_xor_sync(0xffffffffu, s, o);
                float inv = 1.0f / s;
                sw[lane] = e0 * inv; sw[lane + 32] = e1 * inv;
                sw[lane + 64] = e2 * inv; sw[lane + 96] = e3 * inv;
            }
            __syncthreads();
            if (tid < Sc) att[((size_t)b * Tc + t) * Sc + tid] = sw[tid];
            // ctx: 2 cols per thread
            {
                int c0 = tid, c1 = tid + 256;
                const float* e0p = enc + (size_t)b * Sc * Hc + c0;
                const float* e1p = enc + (size_t)b * Sc * Hc + c1;
                float a0 = 0.f, a1 = 0.f;
#pragma unroll 8
                for (int s = 0; s < Sc; s++) {
                    float w = sw[s];
                    a0 += w * e0p[(size_t)s * Hc];
                    a1 += w * e1p[(size_t)s * Hc];
                }
                split2(a0, g_ctxH + b * Hc + c0, g_ctxL + b * Hc + c0);
                split2(a1, g_ctxH + b * Hc + c1, g_ctxL + b * Hc + c1);
            }
        }
        GRID_BAR();

        // ---- phase 3: giC partials = ctx @ WihC^T, 12 N-tiles x 4 K-splits --
        if (bid < 48) {
            int n0 = (bid % 12) * 128, kz = bid / 12;
            mma_tile(sm, g_ctxH, g_ctxL, g_WihCH, g_WihCL, nullptr,
                     g_giC4 + (size_t)kz * Bc * 1536,
                     0, n0, kz * 128, 128 / KC, 1536, 0, 3);
        }
        GRID_BAR();

        // ---- phase 4: gates (block = batch row, 2 j per thread) -------------
        {
            int b = bid;
            size_t r = (size_t)t * Bc + b;
#pragma unroll
            for (int jj = 0; jj < 2; jj++) {
                int j = tid + jj * 256;
                float ghr = 0.f, ghz = 0.f, ghn = 0.f, cr = 0.f, cz = 0.f, cn = 0.f;
#pragma unroll
                for (int p = 0; p < 4; p++) {
                    const float* A4 = g_A4 + (size_t)p * Bc * 2048 + b * 2048 + 512;
                    ghr += A4[j]; ghz += A4[Hc + j]; ghn += A4[2 * Hc + j];
                    const float* C4 = g_giC4 + (size_t)p * Bc * 1536 + b * 1536;
                    cr += C4[j]; cz += C4[Hc + j]; cn += C4[2 * Hc + j];
                }
                const float* giE = g_giE + r * (3 * Hc);
                float rr = sigm(giE[j] + cr + b_ih[j] + ghr + b_hh[j]);
                float z  = sigm(giE[Hc + j] + cz + b_ih[Hc + j] + ghz + b_hh[Hc + j]);
                float n  = tanhf(giE[2 * Hc + j] + cn + b_ih[2 * Hc + j]
                                 + rr * (ghn + b_hh[2 * Hc + j]));
                float hp = g_h[b * Hc + j];
                float hn = (1.0f - z) * n + z * hp;
                g_h[b * Hc + j] = hn;
                split2(hn, g_hhi + b * Hc + j, g_hlo + b * Hc + j);
                split2(hn, g_hallH + r * Hc + j, g_hallL + r * Hc + j);
            }
        }
        GRID_BAR();
    }
#undef GRID_BAR
}

// ---------------- online log_softmax over V, one block per (b,t) row ---------
__global__ __launch_bounds__(512) void lsm_kernel(float* __restrict__ base)
{
    float4* row = (float4*)(base + (size_t)blockIdx.x * Vc);
    const int NV4 = Vc / 4;
    __shared__ float redm[16], reds[16];
    int tid = threadIdx.x, lane = tid & 31, w = tid >> 5;

    float m = -3.4e38f, s = 0.f;
    for (int v = tid; v < NV4; v += 512) {
        float4 x = row[v];
        float lm = fmaxf(fmaxf(x.x, x.y), fmaxf(x.z, x.w));
        float nm = fmaxf(m, lm);
        s = s * __expf(m - nm) + __expf(x.x - nm) + __expf(x.y - nm)
            + __expf(x.z - nm) + __expf(x.w - nm);
        m = nm;
    }
#pragma unroll
    for (int o = 16; o; o >>= 1) {
        float om = __shfl_xor_sync(0xffffffffu, m, o);
        float os = __shfl_xor_sync(0xffffffffu, s, o);
        float nm = fmaxf(m, om);
        s = s * __expf(m - nm) + os * __expf(om - nm);
        m = nm;
    }
    if (!lane) { redm[w] = m; reds[w] = s; }
    __syncthreads();
    float M = redm[0], S = reds[0];
#pragma unroll
    for (int i = 1; i < 16; i++) {
        float nm = fmaxf(M, redm[i]);
        S = S * __expf(M - nm) + reds[i] * __expf(redm[i] - nm);
        M = nm;
    }
    float ls = M + logf(S);
    for (int v = tid; v < NV4; v += 512) {
        float4 x = row[v];
        x.x -= ls; x.y -= ls; x.z -= ls; x.w -= ls;
        row[v] = x;
    }
}

// ---------------- launch ----------------
extern "C" void kernel_launch(void* const* d_in, const int* in_sizes, int n_in,
                              void* d_out, int out_size)
{
    const float* enc  = (const float*)d_in[0];
    const float* h0   = (const float*)d_in[1];
    const int*   tgt  = (const int*)d_in[2];
    const float* emb  = (const float*)d_in[3];
    const float* Wa   = (const float*)d_in[4];
    const float* ba   = (const float*)d_in[5];
    const float* Ua   = (const float*)d_in[6];
    const float* bu   = (const float*)d_in[7];
    const float* Va   = (const float*)d_in[8];
    /* d_in[9] = bv : cancels inside softmax, never observable */
    const float* W_ih = (const float*)d_in[10];
    const float* W_hh = (const float*)d_in[11];
    const float* b_ih = (const float*)d_in[12];
    const float* b_hh = (const float*)d_in[13];
    const float* Wout = (const float*)d_in[14];
    const float* bout = (const float*)d_in[15];

    float* out  = (float*)d_out;
    float* logp = out;                                    // [B,T,V]
    float* hf   = out + (size_t)Bc * Tc * Vc;             // [1,B,H]
    float* att  = hf + (size_t)Bc * Hc;                   // [B,T,S]

    void *p_WoutH, *p_WoutL, *p_BcatH, *p_BcatL, *p_WihEH, *p_WihEL;
    void *p_UaTH, *p_UaTL, *p_encH, *p_encL, *p_xeH, *p_xeL;
    void *p_hallH, *p_hallL, *p_Uk, *p_giE;
    cudaGetSymbolAddress(&p_WoutH, g_WoutH); cudaGetSymbolAddress(&p_WoutL, g_WoutL);
    cudaGetSymbolAddress(&p_BcatH, g_BcatH); cudaGetSymbolAddress(&p_BcatL, g_BcatL);
    cudaGetSymbolAddress(&p_WihEH, g_WihEH); cudaGetSymbolAddress(&p_WihEL, g_WihEL);
    cudaGetSymbolAddress(&p_UaTH, g_UaTH);   cudaGetSymbolAddress(&p_UaTL, g_UaTL);
    cudaGetSymbolAddress(&p_encH, g_encH);   cudaGetSymbolAddress(&p_encL, g_encL);
    cudaGetSymbolAddress(&p_xeH, g_xeH);     cudaGetSymbolAddress(&p_xeL, g_xeL);
    cudaGetSymbolAddress(&p_hallH, g_hallH); cudaGetSymbolAddress(&p_hallL, g_hallL);
    cudaGetSymbolAddress(&p_Uk, g_Uk);       cudaGetSymbolAddress(&p_giE, g_giE);

    // ---- setup conversions ----
    split_kernel<<<(Vc * Hc) / 1024, 256>>>(Wout, (bf16*)p_WoutH, (bf16*)p_WoutL, Vc * Hc);
    split_kernel<<<(3 * Hc * Hc) / 1024, 256>>>(W_hh, (bf16*)p_BcatH + 512 * Hc,
                                                (bf16*)p_BcatL + 512 * Hc, 3 * Hc * Hc);
    splitT_kernel<<<(Hc * Hc) / 256, 256>>>(Wa, (bf16*)p_BcatH, (bf16*)p_BcatL);
    splitT_kernel<<<(Hc * Hc) / 256, 256>>>(Ua, (bf16*)p_UaTH, (bf16*)p_UaTL);
    splitWih_kernel<<<(3 * Hc * Hc) / 256, 256>>>(W_ih);
    split_kernel<<<(Bc * Sc * Hc) / 1024, 256>>>(enc, (bf16*)p_encH, (bf16*)p_encL, Bc * Sc * Hc);

    inith_kernel<<<(Bc * Hc + 255) / 256, 256>>>(h0);
    xe_kernel<<<dim3(Tc, Bc), 128>>>(emb, tgt);

    // Uk = enc @ UaT^T + bu : M=8192, N=512, K=512
    mma_nt_kernel<<<dim3(4, 128), 256>>>((bf16*)p_encH, (bf16*)p_encL,
                                         (bf16*)p_UaTH, (bf16*)p_UaTL,
                                         bu, (float*)p_Uk, Hc, (size_t)Hc, 0, 3);
    // giE = xe @ WihE^T : M=4096, N=1536, K=512
    mma_nt_kernel<<<dim3(12, 64), 256>>>((bf16*)p_xeH, (bf16*)p_xeL,
                                         (bf16*)p_WihEH, (bf16*)p_WihEL,
                                         nullptr, (float*)p_giE, Hc, (size_t)(3 * Hc), 0, 3);

    // ---- the whole recurrent loop in ONE persistent kernel ----
    loop_kernel<<<NBLK, 256>>>(enc, Va, ba, b_ih, b_hh, att);

    // logits for ALL steps: [4096, 32000] = h_all @ Wout^T + bout -> [B,T,V]
    // 2-term split (A_hi x B_hi + A_hi x B_lo): logits don't feed the recurrence.
    mma_nt_kernel<<<dim3(Vc / 128, 64), 256>>>((bf16*)p_hallH, (bf16*)p_hallL,
                                               (bf16*)p_WoutH, (bf16*)p_WoutL,
                                               bout, logp, Hc, 0, 1, 2);
    lsm_kernel<<<Bc * Tc, 512>>>(logp);

    final_h_kernel<<<(Bc * Hc + 255) / 256, 256>>>(hf);
}

// round 9
// speedup vs baseline: 7.3254x; 1.2556x over previous
#include <cuda_runtime.h>
#include <cuda_bf16.h>
#include <math.h>
#include <stdint.h>

#define Bc 64
#define Sc 128
#define Tc 64
#define Hc 512
#define Vc 32000
#define NBLK 64

typedef __nv_bfloat16 bf16;

// ---------------- scratch (device globals: no allocs allowed) ----------------
__device__ __align__(16) float g_Uk[(size_t)Bc * Sc * Hc];       // 16 MB
__device__ __align__(16) float g_h[Bc * Hc];
__device__ __align__(16) bf16  g_hhi[Bc * Hc], g_hlo[Bc * Hc];
__device__ __align__(16) float g_A4[4 * Bc * 2048];              // K-split partials [hwa|gh]
__device__ __align__(16) float g_giC4[4 * Bc * 1536];            // K-split partials giC
__device__ __align__(16) float g_giE[(size_t)Tc * Bc * 3 * Hc];  // 25 MB
__device__ __align__(16) bf16  g_xeH[(size_t)Tc * Bc * Hc], g_xeL[(size_t)Tc * Bc * Hc];
__device__ __align__(16) bf16  g_ctxH[Bc * Hc], g_ctxL[Bc * Hc];
__device__ __align__(16) bf16  g_hallH[(size_t)Tc * Bc * Hc], g_hallL[(size_t)Tc * Bc * Hc];
__device__ __align__(16) bf16  g_WoutH[(size_t)Vc * Hc], g_WoutL[(size_t)Vc * Hc];
__device__ __align__(16) bf16  g_BcatH[2048 * Hc], g_BcatL[2048 * Hc]; // [WaT|W_hh]
__device__ __align__(16) bf16  g_WihEH[3 * Hc * Hc], g_WihEL[3 * Hc * Hc];
__device__ __align__(16) bf16  g_WihCH[3 * Hc * Hc], g_WihCL[3 * Hc * Hc];
__device__ __align__(16) bf16  g_UaTH[Hc * Hc], g_UaTL[Hc * Hc];
__device__ __align__(16) bf16  g_encH[(size_t)Bc * Sc * Hc], g_encL[(size_t)Bc * Sc * Hc];
__device__ unsigned int g_barrier;

__device__ __forceinline__ float sigm(float x) { return 1.0f / (1.0f + expf(-x)); }
__device__ __forceinline__ float fast_tanh(float x) {
    float y; asm("tanh.approx.f32 %0, %1;" : "=f"(y) : "f"(x)); return y;
}
__device__ __forceinline__ void split2(float x, bf16* hi, bf16* lo) {
    bf16 h = __float2bfloat16(x);
    *hi = h;
    *lo = __float2bfloat16(x - __bfloat162float(h));
}

// ---------------- conversion kernels ----------------
__global__ void split_kernel(const float* __restrict__ src, bf16* __restrict__ hi,
                             bf16* __restrict__ lo, int n)
{
    int i = (blockIdx.x * 256 + threadIdx.x) * 4;
    if (i >= n) return;
    float4 v = *(const float4*)(src + i);
    split2(v.x, hi + i + 0, lo + i + 0);
    split2(v.y, hi + i + 1, lo + i + 1);
    split2(v.z, hi + i + 2, lo + i + 2);
    split2(v.w, hi + i + 3, lo + i + 3);
}

__global__ void splitT_kernel(const float* __restrict__ src, bf16* __restrict__ hi,
                              bf16* __restrict__ lo)
{
    int idx = blockIdx.x * 256 + threadIdx.x;
    int k = idx >> 9, n = idx & 511;
    split2(src[idx], hi + n * Hc + k, lo + n * Hc + k);
}

__global__ void splitWih_kernel(const float* __restrict__ W)
{
    int idx = blockIdx.x * 256 + threadIdx.x;   // over 1536*512
    int r = idx >> 9, c = idx & 511;
    split2(W[(size_t)r * 1024 + c], g_WihEH + idx, g_WihEL + idx);
    split2(W[(size_t)r * 1024 + 512 + c], g_WihCH + idx, g_WihCL + idx);
}

__global__ void inith_kernel(const float* __restrict__ h0) {
    int i = blockIdx.x * 256 + threadIdx.x;
    if (i == 0) g_barrier = 0u;
    if (i < Bc * Hc) {
        float v = h0[i];
        g_h[i] = v;
        split2(v, g_hhi + i, g_hlo + i);
    }
}
__global__ void final_h_kernel(float* __restrict__ dst) {
    int i = blockIdx.x * 256 + threadIdx.x;
    if (i < Bc * Hc) dst[i] = g_h[i];
}

__global__ void xe_kernel(const float* __restrict__ emb, const int* __restrict__ tgt) {
    int t = blockIdx.x, b = blockIdx.y;
    int tok = (t == 0) ? 0 : tgt[b * Tc + t - 1];
    size_t base = ((size_t)t * Bc + b) * Hc;
    const float* e = emb + (size_t)tok * Hc;
    for (int k = threadIdx.x; k < Hc; k += 128)
        split2(e[k], g_xeH + base + k, g_xeL + base + k);
}

// ---------------- MMA building blocks -----------------------------------------
#define KC 16
#define LDApad 24
#define OFF_AH 0
#define OFF_AL (64 * LDApad)
#define OFF_BH (128 * LDApad)
#define OFF_BL (256 * LDApad)
#define STG_ELEMS (384 * LDApad)

#define MMA_BF16(c, a, b0_, b1_)                                           \
    asm volatile(                                                          \
        "mma.sync.aligned.m16n8k16.row.col.f32.bf16.bf16.f32 "             \
        "{%0,%1,%2,%3},{%4,%5,%6,%7},{%8,%9},{%0,%1,%2,%3};"               \
        : "+f"(c[0]), "+f"(c[1]), "+f"(c[2]), "+f"(c[3])                   \
        : "r"(a[0]), "r"(a[1]), "r"(a[2]), "r"(a[3]), "r"(b0_), "r"(b1_))

#define LDSM4(r, addr)                                                     \
    asm volatile("ldmatrix.sync.aligned.m8n8.x4.shared.b16 {%0,%1,%2,%3}, [%4];" \
        : "=r"(r[0]), "=r"(r[1]), "=r"(r[2]), "=r"(r[3]) : "r"(addr))

__device__ __forceinline__ void cpa16(uint32_t dst, const void* src) {
    asm volatile("cp.async.ca.shared.global [%0], [%1], 16;" :: "r"(dst), "l"(src));
}

// 64(M) x 128(N) tile, KC=16 2-stage cp.async pipeline, lda/ldb = 512, ldmatrix frags.
__device__ __forceinline__ void mma_tile(
    bf16* sm, const bf16* Ahi, const bf16* Alo,
    const bf16* Bhi, const bf16* Blo,
    const float* bias, float* out,
    int m0, int n0, int kb, int niters, size_t ldc, int scatter, int nterms)
{
    uint32_t sb = (uint32_t)__cvta_generic_to_shared(sm);
    int tid = threadIdx.x, lane = tid & 31, wid = tid >> 5;
    int g = lane >> 2, t4 = lane & 3;
    int wy = wid & 3, wx = wid >> 2;

    // cp.async assignments
    int ac = tid & 127, arow = ac >> 1, ao8 = (ac & 1) * 8;
    const bf16* aptr = (tid < 128 ? Ahi : Alo) + (size_t)(m0 + arow) * 512 + ao8;
    uint32_t adst = sb + 2 * ((tid < 128 ? OFF_AH : OFF_AL) + arow * LDApad + ao8);
    int brow = tid >> 1, bo8 = (tid & 1) * 8;
    const bf16* bhp = Bhi + (size_t)(n0 + brow) * 512 + bo8;
    const bf16* blp = Blo + (size_t)(n0 + brow) * 512 + bo8;
    uint32_t bhd = sb + 2 * (OFF_BH + brow * LDApad + bo8);
    uint32_t bld = sb + 2 * (OFF_BL + brow * LDApad + bo8);

    // ldmatrix lane addresses (element offsets)
    int la = (wy * 16 + (lane & 15)) * LDApad + (lane >> 4) * 8;
    int nloc = (lane & 7) | ((lane & 16) >> 1);
    int kq2 = ((lane >> 3) & 1) * 8;
    int lb = (wx * 64 + nloc) * LDApad + kq2;

    float acc[8][4] = {};

    cpa16(adst, aptr + kb);
    cpa16(bhd, bhp + kb);
    cpa16(bld, blp + kb);
    asm volatile("cp.async.commit_group;");

    int st = 0;
    for (int it = 0; it < niters; it++) {
        if (it + 1 < niters) {
            int kn = kb + (it + 1) * KC;
            uint32_t so = (uint32_t)((st ^ 1) * STG_ELEMS * 2);
            cpa16(adst + so, aptr + kn);
            cpa16(bhd + so, bhp + kn);
            cpa16(bld + so, blp + kn);
            asm volatile("cp.async.commit_group;");
            asm volatile("cp.async.wait_group 1;");
        } else {
            asm volatile("cp.async.wait_group 0;");
        }
        __syncthreads();

        uint32_t stoff = (uint32_t)(st * STG_ELEMS * 2);
        uint32_t aH[4], aL[4];
        LDSM4(aH, sb + stoff + 2 * (OFF_AH + la));
        if (nterms == 3) LDSM4(aL, sb + stoff + 2 * (OFF_AL + la));
#pragma unroll
        for (int q = 0; q < 4; q++) {
            uint32_t bH[4], bL[4];
            LDSM4(bH, sb + stoff + 2 * (OFF_BH + lb + q * 16 * LDApad));
            LDSM4(bL, sb + stoff + 2 * (OFF_BL + lb + q * 16 * LDApad));
            MMA_BF16(acc[2 * q],     aH, bH[0], bH[1]);
            MMA_BF16(acc[2 * q + 1], aH, bH[2], bH[3]);
            MMA_BF16(acc[2 * q],     aH, bL[0], bL[1]);
            MMA_BF16(acc[2 * q + 1], aH, bL[2], bL[3]);
            if (nterms == 3) {
                MMA_BF16(acc[2 * q],     aL, bH[0], bH[1]);
                MMA_BF16(acc[2 * q + 1], aL, bH[2], bH[3]);
            }
        }
        __syncthreads();
        st ^= 1;
    }

    int mr0 = m0 + wy * 16 + g, mr1 = mr0 + 8;
    size_t ro0, ro1;
    if (scatter) {
        ro0 = ((size_t)(mr0 & 63) * Tc + (mr0 >> 6)) * Vc;
        ro1 = ((size_t)(mr1 & 63) * Tc + (mr1 >> 6)) * Vc;
    } else {
        ro0 = (size_t)mr0 * ldc;
        ro1 = (size_t)mr1 * ldc;
    }
#pragma unroll
    for (int nf = 0; nf < 8; nf++) {
        int col = n0 + wx * 64 + nf * 8 + t4 * 2;
        float b0 = bias ? bias[col] : 0.f;
        float b1 = bias ? bias[col + 1] : 0.f;
        out[ro0 + col]     = acc[nf][0] + b0;
        out[ro0 + col + 1] = acc[nf][1] + b1;
        out[ro1 + col]     = acc[nf][2] + b0;
        out[ro1 + col + 1] = acc[nf][3] + b1;
    }
}

// ---------------- standalone MMA kernel (Uk, giE) ----------------------------
__global__ __launch_bounds__(256) void mma_nt_kernel(
    const bf16* __restrict__ Ahi, const bf16* __restrict__ Alo,
    const bf16* __restrict__ Bhi, const bf16* __restrict__ Blo,
    const float* __restrict__ bias, float* __restrict__ out,
    int Kcp, size_t ldc, int scatter, int nterms)
{
    __shared__ __align__(16) bf16 sm[2 * STG_ELEMS];
    mma_tile(sm, Ahi, Alo, Bhi, Blo, bias, out,
             blockIdx.y * 64, blockIdx.x * 128, 0, Kcp / KC, ldc, scatter, nterms);
}

// ---------------- dedicated logits kernel: M-tile 128, 2-term, scatter -------
// A region: 128 rows hi only; B: hi+lo. Same smem as mma_tile (36.9 KB).
#define LG_AH 0
#define LG_BH (128 * LDApad)
#define LG_BL (256 * LDApad)

__global__ __launch_bounds__(256) void logits_kernel(
    const bf16* __restrict__ Ahi, const bf16* __restrict__ Bhi,
    const bf16* __restrict__ Blo, const float* __restrict__ bias,
    float* __restrict__ out)
{
    __shared__ __align__(16) bf16 sm[2 * STG_ELEMS];
    uint32_t sb = (uint32_t)__cvta_generic_to_shared(sm);
    int tid = threadIdx.x, lane = tid & 31, wid = tid >> 5;
    int g = lane >> 2, t4 = lane & 3;
    int wy = wid & 3, wx = wid >> 2;
    int m0 = blockIdx.y * 128, n0 = blockIdx.x * 128;

    int arow = tid >> 1, ao8 = (tid & 1) * 8;   // 128 rows x 2 chunks
    const bf16* aptr = Ahi + (size_t)(m0 + arow) * 512 + ao8;
    uint32_t adst = sb + 2 * (LG_AH + arow * LDApad + ao8);
    const bf16* bhp = Bhi + (size_t)(n0 + arow) * 512 + ao8;
    const bf16* blp = Blo + (size_t)(n0 + arow) * 512 + ao8;
    uint32_t bhd = sb + 2 * (LG_BH + arow * LDApad + ao8);
    uint32_t bld = sb + 2 * (LG_BL + arow * LDApad + ao8);

    int la = (wy * 16 + (lane & 15)) * LDApad + (lane >> 4) * 8;
    int nloc = (lane & 7) | ((lane & 16) >> 1);
    int kq2 = ((lane >> 3) & 1) * 8;
    int lb = (wx * 64 + nloc) * LDApad + kq2;

    float acc[2][8][4] = {};

    cpa16(adst, aptr);
    cpa16(bhd, bhp);
    cpa16(bld, blp);
    asm volatile("cp.async.commit_group;");

    int st = 0;
    const int niters = Hc / KC;   // 32
    for (int it = 0; it < niters; it++) {
        if (it + 1 < niters) {
            int kn = (it + 1) * KC;
            uint32_t so = (uint32_t)((st ^ 1) * STG_ELEMS * 2);
            cpa16(adst + so, aptr + kn);
            cpa16(bhd + so, bhp + kn);
            cpa16(bld + so, blp + kn);
            asm volatile("cp.async.commit_group;");
            asm volatile("cp.async.wait_group 1;");
        } else {
            asm volatile("cp.async.wait_group 0;");
        }
        __syncthreads();

        uint32_t stoff = (uint32_t)(st * STG_ELEMS * 2);
        uint32_t aH0[4], aH1[4];
        LDSM4(aH0, sb + stoff + 2 * (LG_AH + la));
        LDSM4(aH1, sb + stoff + 2 * (LG_AH + 64 * LDApad + la));
#pragma unroll
        for (int q = 0; q < 4; q++) {
            uint32_t bH[4], bL[4];
            LDSM4(bH, sb + stoff + 2 * (LG_BH + lb + q * 16 * LDApad));
            LDSM4(bL, sb + stoff + 2 * (LG_BL + lb + q * 16 * LDApad));
            MMA_BF16(acc[0][2 * q],     aH0, bH[0], bH[1]);
            MMA_BF16(acc[0][2 * q + 1], aH0, bH[2], bH[3]);
            MMA_BF16(acc[1][2 * q],     aH1, bH[0], bH[1]);
            MMA_BF16(acc[1][2 * q + 1], aH1, bH[2], bH[3]);
            MMA_BF16(acc[0][2 * q],     aH0, bL[0], bL[1]);
            MMA_BF16(acc[0][2 * q + 1], aH0, bL[2], bL[3]);
            MMA_BF16(acc[1][2 * q],     aH1, bL[0], bL[1]);
            MMA_BF16(acc[1][2 * q + 1], aH1, bL[2], bL[3]);
        }
        __syncthreads();
        st ^= 1;
    }

#pragma unroll
    for (int ms = 0; ms < 2; ms++) {
        int mr0 = m0 + ms * 64 + wy * 16 + g, mr1 = mr0 + 8;
        size_t ro0 = ((size_t)(mr0 & 63) * Tc + (mr0 >> 6)) * Vc;
        size_t ro1 = ((size_t)(mr1 & 63) * Tc + (mr1 >> 6)) * Vc;
#pragma unroll
        for (int nf = 0; nf < 8; nf++) {
            int col = n0 + wx * 64 + nf * 8 + t4 * 2;
            float b0 = bias[col], b1 = bias[col + 1];
            out[ro0 + col]     = acc[ms][nf][0] + b0;
            out[ro0 + col + 1] = acc[ms][nf][1] + b1;
            out[ro1 + col]     = acc[ms][nf][2] + b0;
            out[ro1 + col + 1] = acc[ms][nf][3] + b1;
        }
    }
}

// ---------------- persistent loop kernel --------------------------------------
__global__ __launch_bounds__(256) void loop_kernel(
    const float* __restrict__ enc, const float* __restrict__ Va,
    const float* __restrict__ ba, const float* __restrict__ b_ih,
    const float* __restrict__ b_hh, float* __restrict__ att)
{
    __shared__ __align__(16) bf16 sm[2 * STG_ELEMS];   // 36.9 KB, reused by attn
    int bid = blockIdx.x, tid = threadIdx.x;
    int lane = tid & 31, warp = tid >> 5;
    unsigned int gen = 0;

    float* shwa = (float*)sm;          // 512
    float* sva  = shwa + 512;          // 512
    float* sw   = sva + 512;           // 128

#define GRID_BAR()                                                             \
    do {                                                                       \
        __syncthreads();                                                       \
        gen += NBLK;                                                           \
        if (tid == 0) {                                                        \
            asm volatile("red.release.gpu.global.add.u32 [%0], 1;"             \
                         :: "l"(&g_barrier) : "memory");                       \
            unsigned int v;                                                    \
            do {                                                               \
                asm volatile("ld.acquire.gpu.global.u32 %0, [%1];"             \
                             : "=r"(v) : "l"(&g_barrier) : "memory");          \
            } while (v < gen);                                                 \
        }                                                                      \
        __syncthreads();                                                       \
    } while (0)

    for (int t = 0; t < Tc; t++) {
        // ---- phase 1: [hwa|gh] partials = h @ Bcat^T, 16 N-tiles x 4 K-splits
        {
            int n0 = (bid & 15) * 128, kz = bid >> 4;
            mma_tile(sm, g_hhi, g_hlo, g_BcatH, g_BcatL, nullptr,
                     g_A4 + (size_t)kz * Bc * 2048,
                     0, n0, kz * 128, 128 / KC, 2048, 0, 3);
        }
        GRID_BAR();

        // ---- phase 2: fused scores + softmax + ctx (block = batch row) ------
        {
            int b = bid;
            for (int i = tid; i < Hc; i += 256) {
                float v = ba[i];
#pragma unroll
                for (int p = 0; p < 4; p++) v += g_A4[(size_t)p * Bc * 2048 + b * 2048 + i];
                shwa[i] = v;
                sva[i] = Va[i];
            }
            __syncthreads();
#pragma unroll 2
            for (int si = 0; si < 16; si++) {
                int s = warp * 16 + si;
                const float* uk = g_Uk + ((size_t)b * Sc + s) * Hc;
                float acc = 0.f;
#pragma unroll
                for (int j = 0; j < 4; j++) {
                    int k = j * 128 + lane * 4;
                    float4 u  = *(const float4*)(uk + k);
                    float4 wv = *(const float4*)(shwa + k);
                    float4 vv = *(const float4*)(sva + k);
                    acc += fast_tanh(wv.x + u.x) * vv.x + fast_tanh(wv.y + u.y) * vv.y
                         + fast_tanh(wv.z + u.z) * vv.z + fast_tanh(wv.w + u.w) * vv.w;
                }
#pragma unroll
                for (int o = 16; o; o >>= 1) acc += __shfl_xor_sync(0xffffffffu, acc, o);
                if (!lane) sw[s] = acc;    // bv cancels in softmax
            }
            __syncthreads();
            if (warp == 0) {
                float v0 = sw[lane], v1 = sw[lane + 32], v2 = sw[lane + 64], v3 = sw[lane + 96];
                float m = fmaxf(fmaxf(v0, v1), fmaxf(v2, v3));
#pragma unroll
                for (int o = 16; o; o >>= 1) m = fmaxf(m, __shfl_xor_sync(0xffffffffu, m, o));
                float e0 = expf(v0 - m), e1 = expf(v1 - m), e2 = expf(v2 - m), e3 = expf(v3 - m);
                float s = e0 + e1 + e2 + e3;
#pragma unroll
                for (int o = 16; o; o >>= 1) s += __shfl_xor_sync(0xffffffffu, s, o);
                float inv = 1.0f / s;
                sw[lane] = e0 * inv; sw[lane + 32] = e1 * inv;
                sw[lane + 64] = e2 * inv; sw[lane + 96] = e3 * inv;
            }
            __syncthreads();
            if (tid < Sc) att[((size_t)b * Tc + t) * Sc + tid] = sw[tid];
            {
                int c0 = tid, c1 = tid + 256;
                const float* e0p = enc + (size_t)b * Sc * Hc + c0;
                const float* e1p = enc + (size_t)b * Sc * Hc + c1;
                float a0 = 0.f, a1 = 0.f;
#pragma unroll 8
                for (int s = 0; s < Sc; s++) {
                    float w = sw[s];
                    a0 += w * e0p[(size_t)s * Hc];
                    a1 += w * e1p[(size_t)s * Hc];
                }
                split2(a0, g_ctxH + b * Hc + c0, g_ctxL + b * Hc + c0);
                split2(a1, g_ctxH + b * Hc + c1, g_ctxL + b * Hc + c1);
            }
        }
        GRID_BAR();

        // ---- phase 3: giC partials = ctx @ WihC^T, 12 N-tiles x 4 K-splits --
        if (bid < 48) {
            int n0 = (bid % 12) * 128, kz = bid / 12;
            mma_tile(sm, g_ctxH, g_ctxL, g_WihCH, g_WihCL, nullptr,
                     g_giC4 + (size_t)kz * Bc * 1536,
                     0, n0, kz * 128, 128 / KC, 1536, 0, 3);
        }
        GRID_BAR();

        // ---- phase 4: gates (block = batch row, 2 j per thread) -------------
        {
            int b = bid;
            size_t r = (size_t)t * Bc + b;
#pragma unroll
            for (int jj = 0; jj < 2; jj++) {
                int j = tid + jj * 256;
                float ghr = 0.f, ghz = 0.f, ghn = 0.f, cr = 0.f, cz = 0.f, cn = 0.f;
#pragma unroll
                for (int p = 0; p < 4; p++) {
                    const float* A4 = g_A4 + (size_t)p * Bc * 2048 + b * 2048 + 512;
                    ghr += A4[j]; ghz += A4[Hc + j]; ghn += A4[2 * Hc + j];
                    const float* C4 = g_giC4 + (size_t)p * Bc * 1536 + b * 1536;
                    cr += C4[j]; cz += C4[Hc + j]; cn += C4[2 * Hc + j];
                }
                const float* giE = g_giE + r * (3 * Hc);
                float rr = sigm(giE[j] + cr + b_ih[j] + ghr + b_hh[j]);
                float z  = sigm(giE[Hc + j] + cz + b_ih[Hc + j] + ghz + b_hh[Hc + j]);
                float n  = tanhf(giE[2 * Hc + j] + cn + b_ih[2 * Hc + j]
                                 + rr * (ghn + b_hh[2 * Hc + j]));
                float hp = g_h[b * Hc + j];
                float hn = (1.0f - z) * n + z * hp;
                g_h[b * Hc + j] = hn;
                split2(hn, g_hhi + b * Hc + j, g_hlo + b * Hc + j);
                split2(hn, g_hallH + r * Hc + j, g_hallL + r * Hc + j);
            }
        }
        GRID_BAR();
    }
#undef GRID_BAR
}

// ---------------- online log_softmax over V, one block per (b,t) row ---------
__global__ __launch_bounds__(512) void lsm_kernel(float* __restrict__ base)
{
    float4* row = (float4*)(base + (size_t)blockIdx.x * Vc);
    const int NV4 = Vc / 4;
    __shared__ float redm[16], reds[16];
    int tid = threadIdx.x, lane = tid & 31, w = tid >> 5;

    float m = -3.4e38f, s = 0.f;
    for (int v = tid; v < NV4; v += 512) {
        float4 x = row[v];
        float lm = fmaxf(fmaxf(x.x, x.y), fmaxf(x.z, x.w));
        float nm = fmaxf(m, lm);
        s = s * __expf(m - nm) + __expf(x.x - nm) + __expf(x.y - nm)
            + __expf(x.z - nm) + __expf(x.w - nm);
        m = nm;
    }
#pragma unroll
    for (int o = 16; o; o >>= 1) {
        float om = __shfl_xor_sync(0xffffffffu, m, o);
        float os = __shfl_xor_sync(0xffffffffu, s, o);
        float nm = fmaxf(m, om);
        s = s * __expf(m - nm) + os * __expf(om - nm);
        m = nm;
    }
    if (!lane) { redm[w] = m; reds[w] = s; }
    __syncthreads();
    float M = redm[0], S = reds[0];
#pragma unroll
    for (int i = 1; i < 16; i++) {
        float nm = fmaxf(M, redm[i]);
        S = S * __expf(M - nm) + reds[i] * __expf(redm[i] - nm);
        M = nm;
    }
    float ls = M + logf(S);
    for (int v = tid; v < NV4; v += 512) {
        float4 x = row[v];
        x.x -= ls; x.y -= ls; x.z -= ls; x.w -= ls;
        row[v] = x;
    }
}

// ---------------- launch ----------------
extern "C" void kernel_launch(void* const* d_in, const int* in_sizes, int n_in,
                              void* d_out, int out_size)
{
    const float* enc  = (const float*)d_in[0];
    const float* h0   = (const float*)d_in[1];
    const int*   tgt  = (const int*)d_in[2];
    const float* emb  = (const float*)d_in[3];
    const float* Wa   = (const float*)d_in[4];
    const float* ba   = (const float*)d_in[5];
    const float* Ua   = (const float*)d_in[6];
    const float* bu   = (const float*)d_in[7];
    const float* Va   = (const float*)d_in[8];
    /* d_in[9] = bv : cancels inside softmax, never observable */
    const float* W_ih = (const float*)d_in[10];
    const float* W_hh = (const float*)d_in[11];
    const float* b_ih = (const float*)d_in[12];
    const float* b_hh = (const float*)d_in[13];
    const float* Wout = (const float*)d_in[14];
    const float* bout = (const float*)d_in[15];

    float* out  = (float*)d_out;
    float* logp = out;                                    // [B,T,V]
    float* hf   = out + (size_t)Bc * Tc * Vc;             // [1,B,H]
    float* att  = hf + (size_t)Bc * Hc;                   // [B,T,S]

    void *p_WoutH, *p_WoutL, *p_BcatH, *p_BcatL, *p_WihEH, *p_WihEL;
    void *p_UaTH, *p_UaTL, *p_encH, *p_encL, *p_xeH, *p_xeL;
    void *p_hallH, *p_Uk, *p_giE;
    cudaGetSymbolAddress(&p_WoutH, g_WoutH); cudaGetSymbolAddress(&p_WoutL, g_WoutL);
    cudaGetSymbolAddress(&p_BcatH, g_BcatH); cudaGetSymbolAddress(&p_BcatL, g_BcatL);
    cudaGetSymbolAddress(&p_WihEH, g_WihEH); cudaGetSymbolAddress(&p_WihEL, g_WihEL);
    cudaGetSymbolAddress(&p_UaTH, g_UaTH);   cudaGetSymbolAddress(&p_UaTL, g_UaTL);
    cudaGetSymbolAddress(&p_encH, g_encH);   cudaGetSymbolAddress(&p_encL, g_encL);
    cudaGetSymbolAddress(&p_xeH, g_xeH);     cudaGetSymbolAddress(&p_xeL, g_xeL);
    cudaGetSymbolAddress(&p_hallH, g_hallH);
    cudaGetSymbolAddress(&p_Uk, g_Uk);       cudaGetSymbolAddress(&p_giE, g_giE);

    // ---- setup conversions ----
    split_kernel<<<(Vc * Hc) / 1024, 256>>>(Wout, (bf16*)p_WoutH, (bf16*)p_WoutL, Vc * Hc);
    split_kernel<<<(3 * Hc * Hc) / 1024, 256>>>(W_hh, (bf16*)p_BcatH + 512 * Hc,
                                                (bf16*)p_BcatL + 512 * Hc, 3 * Hc * Hc);
    splitT_kernel<<<(Hc * Hc) / 256, 256>>>(Wa, (bf16*)p_BcatH, (bf16*)p_BcatL);
    splitT_kernel<<<(Hc * Hc) / 256, 256>>>(Ua, (bf16*)p_UaTH, (bf16*)p_UaTL);
    splitWih_kernel<<<(3 * Hc * Hc) / 256, 256>>>(W_ih);
    split_kernel<<<(Bc * Sc * Hc) / 1024, 256>>>(enc, (bf16*)p_encH, (bf16*)p_encL, Bc * Sc * Hc);

    inith_kernel<<<(Bc * Hc + 255) / 256, 256>>>(h0);
    xe_kernel<<<dim3(Tc, Bc), 128>>>(emb, tgt);

    // Uk = enc @ UaT^T + bu : M=8192, N=512, K=512
    mma_nt_kernel<<<dim3(4, 128), 256>>>((bf16*)p_encH, (bf16*)p_encL,
                                         (bf16*)p_UaTH, (bf16*)p_UaTL,
                                         bu, (float*)p_Uk, Hc, (size_t)Hc, 0, 3);
    // giE = xe @ WihE^T : M=4096, N=1536, K=512
    mma_nt_kernel<<<dim3(12, 64), 256>>>((bf16*)p_xeH, (bf16*)p_xeL,
                                         (bf16*)p_WihEH, (bf16*)p_WihEL,
                                         nullptr, (float*)p_giE, Hc, (size_t)(3 * Hc), 0, 3);

    // ---- the whole recurrent loop in ONE persistent kernel ----
    loop_kernel<<<NBLK, 256>>>(enc, Va, ba, b_ih, b_hh, att);

    // logits for ALL steps: [4096, 32000] = h_all @ Wout^T + bout -> [B,T,V]
    logits_kernel<<<dim3(Vc / 128, 32), 256>>>((bf16*)p_hallH,
                                               (bf16*)p_WoutH, (bf16*)p_WoutL,
                                               bout, logp);
    lsm_kernel<<<Bc * Tc, 512>>>(logp);

    final_h_kernel<<<(Bc * Hc + 255) / 256, 256>>>(hf);
}